// round 12
// baseline (speedup 1.0000x reference)
#include <cuda_runtime.h>
#include <math.h>

// ---------------- Config ----------------
#define BATCH 8
#define CCH   3
#define IMG   384
#define PCH   16
#define GH    24
#define GW    24
#define NP    576           // patches
#define NTOK  577           // +CLS
#define DMODEL 768
#define NHEAD 12
#define HD    64
#define LYRS  12
#define MLPD  3072
#define NCLS  1000

#define TOKS  (BATCH*NTOK)          // 4616
#define PROWS (BATCH*NP)            // 4608
#define SP    592                   // padded S row stride (577 -> 592, mult of 16)

typedef unsigned long long ull;

// ---------------- Scratch (static device globals; no runtime alloc) ----------------
__device__ float g_T[PROWS*DMODEL];      // gathered patch pixels
__device__ float g_E[PROWS*DMODEL];      // patch embeddings
__device__ float g_H[TOKS*DMODEL];       // residual stream
__device__ float g_Y[TOKS*DMODEL];       // LN output
__device__ float g_Q[TOKS*DMODEL];
__device__ float g_K[TOKS*DMODEL];
__device__ float g_V[TOKS*DMODEL];
__device__ float g_O[TOKS*DMODEL];
__device__ float g_S[(size_t)BATCH*NHEAD*NTOK*SP];   // attn probs (padded rows)
__device__ float g_M[(size_t)TOKS*MLPD];             // MLP hidden

// ---------------- f32x2 helpers (sm_103a packed fp32) ----------------
__device__ __forceinline__ ull pack2(float x) {
    ull r;
    unsigned u = __float_as_uint(x);
    asm("mov.b64 %0, {%1, %1};" : "=l"(r) : "r"(u));
    return r;
}
__device__ __forceinline__ void fma2(ull& d, ull a, ull b) {
    asm("fma.rn.f32x2 %0, %1, %2, %0;" : "+l"(d) : "l"(a), "l"(b));
}
__device__ __forceinline__ float2 unpack2(ull v) {
    float2 f;
    asm("mov.b64 {%0, %1}, %2;" : "=f"(f.x), "=f"(f.y) : "l"(v));
    return f;
}

__device__ __forceinline__ float gelu_exact(float x) {
    return 0.5f * x * (1.0f + erff(x * 0.70710678118654752f));
}

// ---------------- Generic GEMM: C = A[MxK] @ B[KxN] + bias (+act) (+res) ----------------
// BM=128, BN=128, BK=16, 256 threads, 8x8 per thread, f32x2 packed FMA.
// Requires: K % 16 == 0, N % 128 == 0. M guarded.
__global__ __launch_bounds__(256, 2) void gemm_kernel(
    const float* __restrict__ A, const float* __restrict__ B,
    const float* __restrict__ bias, const float* __restrict__ res,
    float* __restrict__ C, int M, int N, int K, int act)
{
    __shared__ float As[16][128];   // transposed: As[k][m]
    __shared__ float Bs[16][128];   // Bs[k][n]

    const int bm = blockIdx.y * 128;
    const int bn = blockIdx.x * 128;
    const int tid = threadIdx.x;
    const int ty = tid >> 4, tx = tid & 15;
    const int row0 = ty * 8, col0 = tx * 8;

    ull acc[8][4];
#pragma unroll
    for (int i = 0; i < 8; i++)
#pragma unroll
        for (int j = 0; j < 4; j++) acc[i][j] = 0ULL;

    for (int k0 = 0; k0 < K; k0 += 16) {
#pragma unroll
        for (int i = 0; i < 2; i++) {
            int idx = tid + i * 256;                 // 0..511
            // A tile: 128 rows x 16 k (as 4 float4 per row)
            int r  = idx >> 2;
            int kq = (idx & 3) * 4;
            float4 va = make_float4(0.f, 0.f, 0.f, 0.f);
            if (bm + r < M) va = *(const float4*)(A + (size_t)(bm + r) * K + k0 + kq);
            As[kq + 0][r] = va.x; As[kq + 1][r] = va.y;
            As[kq + 2][r] = va.z; As[kq + 3][r] = va.w;
            // B tile: 16 k x 128 n
            int kk = idx >> 5;
            int nq = (idx & 31) * 4;
            *(float4*)&Bs[kk][nq] =
                *(const float4*)(B + (size_t)(k0 + kk) * N + bn + nq);
        }
        __syncthreads();

#pragma unroll
        for (int k = 0; k < 16; k++) {
            float4 a0 = *(const float4*)&As[k][row0];
            float4 a1 = *(const float4*)&As[k][row0 + 4];
            ull a2r[8];
            a2r[0] = pack2(a0.x); a2r[1] = pack2(a0.y);
            a2r[2] = pack2(a0.z); a2r[3] = pack2(a0.w);
            a2r[4] = pack2(a1.x); a2r[5] = pack2(a1.y);
            a2r[6] = pack2(a1.z); a2r[7] = pack2(a1.w);
            ull b2[4];
            b2[0] = *(const ull*)&Bs[k][col0 + 0];
            b2[1] = *(const ull*)&Bs[k][col0 + 2];
            b2[2] = *(const ull*)&Bs[k][col0 + 4];
            b2[3] = *(const ull*)&Bs[k][col0 + 6];
#pragma unroll
            for (int i = 0; i < 8; i++)
#pragma unroll
                for (int j = 0; j < 4; j++) fma2(acc[i][j], a2r[i], b2[j]);
        }
        __syncthreads();
    }

#pragma unroll
    for (int i = 0; i < 8; i++) {
        int gr = bm + row0 + i;
        if (gr >= M) continue;
        float* crow = C + (size_t)gr * N + bn + col0;
        const float* rrow = res ? (res + (size_t)gr * N + bn + col0) : (const float*)0;
#pragma unroll
        for (int j = 0; j < 4; j++) {
            float2 v = unpack2(acc[i][j]);
            int c = 2 * j;
            float x0 = v.x + bias[bn + col0 + c];
            float x1 = v.y + bias[bn + col0 + c + 1];
            if (act == 1) { x0 = gelu_exact(x0); x1 = gelu_exact(x1); }
            if (rrow) { x0 += rrow[c]; x1 += rrow[c + 1]; }
            crow[c] = x0; crow[c + 1] = x1;
        }
    }
}

// ---------------- Patch gather (faithful buggy flattening) ----------------
// out linear index l over [PROWS*768]:
//   p1 = l / 221184; rem = l % 221184; m = rem/16; p2 = rem%16
//   b = m/1728; c = (m/576)%3; gh = (m/24)%24; gw = m%24
//   val = x[b, c, gh*16+p1, gw*16+p2]
__global__ void patch_gather_kernel(const float* __restrict__ x, float* __restrict__ T)
{
    int idx = blockIdx.x * blockDim.x + threadIdx.x;
    if (idx >= PROWS * DMODEL) return;
    int p1  = idx / 221184;
    int rem = idx % 221184;
    int m   = rem >> 4;
    int p2  = rem & 15;
    int b   = m / 1728;
    int mm  = m - b * 1728;
    int c   = mm / 576;
    int mg  = mm - c * 576;
    int gh  = mg / 24;
    int gw  = mg - gh * 24;
    T[idx] = x[(((size_t)(b * CCH + c) * IMG) + gh * 16 + p1) * IMG + gw * 16 + p2];
}

// ---------------- Assemble tokens: CLS + patches + pos_emb ----------------
__global__ void assemble_kernel(const float* __restrict__ E, const float* __restrict__ cls,
                                const float* __restrict__ pos, float* __restrict__ H)
{
    int idx = blockIdx.x * blockDim.x + threadIdx.x;
    if (idx >= TOKS * DMODEL) return;
    int tok = idx / DMODEL;
    int k   = idx - tok * DMODEL;
    int b   = tok / NTOK;
    int n   = tok - b * NTOK;
    float v = (n == 0) ? cls[k] : E[((size_t)(b * NP + n - 1)) * DMODEL + k];
    H[idx] = v + pos[(size_t)n * DMODEL + k];
}

// ---------------- LayerNorm (row per block, 768 = 3*256) ----------------
__global__ void layernorm_kernel(const float* __restrict__ X, const float* __restrict__ g,
                                 const float* __restrict__ bta, float* __restrict__ Y)
{
    int r = blockIdx.x;
    const float* xr = X + (size_t)r * DMODEL;
    float* yr = Y + (size_t)r * DMODEL;
    int tid = threadIdx.x;
    float v0 = xr[tid], v1 = xr[tid + 256], v2 = xr[tid + 512];
    float s  = v0 + v1 + v2;
    float s2 = v0 * v0 + v1 * v1 + v2 * v2;
#pragma unroll
    for (int o = 16; o; o >>= 1) {
        s  += __shfl_xor_sync(0xffffffffu, s,  o);
        s2 += __shfl_xor_sync(0xffffffffu, s2, o);
    }
    __shared__ float r1[8], r2[8];
    if ((tid & 31) == 0) { r1[tid >> 5] = s; r2[tid >> 5] = s2; }
    __syncthreads();
    float S = 0.f, S2 = 0.f;
#pragma unroll
    for (int w = 0; w < 8; w++) { S += r1[w]; S2 += r2[w]; }
    float mean = S * (1.0f / 768.0f);
    float var  = S2 * (1.0f / 768.0f) - mean * mean;
    float inv  = rsqrtf(var + 1e-5f);
    yr[tid]       = (v0 - mean) * inv * g[tid]       + bta[tid];
    yr[tid + 256] = (v1 - mean) * inv * g[tid + 256] + bta[tid + 256];
    yr[tid + 512] = (v2 - mean) * inv * g[tid + 512] + bta[tid + 512];
}

// ---------------- Attention scores: S[bh] = scale * Q_bh @ K_bh^T ----------------
// grid (10, 10, 96), 256 threads, 64x64 tile, 4x4 per thread.
__global__ __launch_bounds__(256) void attn_scores_kernel(
    const float* __restrict__ Q, const float* __restrict__ K, float* __restrict__ S)
{
    const int bh = blockIdx.z;
    const int b = bh / NHEAD, h = bh - b * NHEAD;
    const float* Qb = Q + (size_t)b * NTOK * DMODEL + h * HD;
    const float* Kb = K + (size_t)b * NTOK * DMODEL + h * HD;
    float* Sb = S + (size_t)bh * NTOK * SP;
    const int m0 = blockIdx.y * 64, n0 = blockIdx.x * 64;

    __shared__ float Qs[64][68];
    __shared__ float Ks[64][68];
    const int tid = threadIdx.x;

#pragma unroll
    for (int i = 0; i < 4; i++) {
        int f4 = tid + i * 256;          // 0..1023
        int r  = f4 >> 4;
        int d4 = (f4 & 15) * 4;
        float4 q = make_float4(0.f, 0.f, 0.f, 0.f), kv = q;
        if (m0 + r < NTOK) q  = *(const float4*)(Qb + (size_t)(m0 + r) * DMODEL + d4);
        if (n0 + r < NTOK) kv = *(const float4*)(Kb + (size_t)(n0 + r) * DMODEL + d4);
        *(float4*)&Qs[r][d4] = q;
        *(float4*)&Ks[r][d4] = kv;
    }
    __syncthreads();

    const int ty = tid >> 4, tx = tid & 15;
    float acc[4][4] = {};
#pragma unroll
    for (int d4 = 0; d4 < 16; d4++) {
        float4 a[4], bb[4];
#pragma unroll
        for (int i = 0; i < 4; i++) a[i]  = *(const float4*)&Qs[ty * 4 + i][d4 * 4];
#pragma unroll
        for (int j = 0; j < 4; j++) bb[j] = *(const float4*)&Ks[tx * 4 + j][d4 * 4];
#pragma unroll
        for (int i = 0; i < 4; i++)
#pragma unroll
            for (int j = 0; j < 4; j++)
                acc[i][j] += a[i].x * bb[j].x + a[i].y * bb[j].y
                           + a[i].z * bb[j].z + a[i].w * bb[j].w;
    }
    const float scale = 0.125f;  // 1/sqrt(64)
#pragma unroll
    for (int i = 0; i < 4; i++) {
        int m = m0 + ty * 4 + i;
        if (m >= NTOK) continue;
#pragma unroll
        for (int j = 0; j < 4; j++) {
            int n = n0 + tx * 4 + j;
            if (n < NTOK) Sb[(size_t)m * SP + n] = acc[i][j] * scale;
        }
    }
}

// ---------------- Row softmax over S (also zeroes pad cols 577..591) ----------------
__global__ void softmax_kernel(float* __restrict__ S)
{
    int r  = blockIdx.x;                    // 0..96*577-1
    int bh = r / NTOK, m = r - bh * NTOK;
    float* row = S + (size_t)bh * NTOK * SP + (size_t)m * SP;
    int tid = threadIdx.x;                  // 128

    float lmax = -3.4e38f;
    for (int c = tid; c < NTOK; c += 128) lmax = fmaxf(lmax, row[c]);
#pragma unroll
    for (int o = 16; o; o >>= 1) lmax = fmaxf(lmax, __shfl_xor_sync(0xffffffffu, lmax, o));
    __shared__ float sred[4];
    if ((tid & 31) == 0) sred[tid >> 5] = lmax;
    __syncthreads();
    float bmax = fmaxf(fmaxf(sred[0], sred[1]), fmaxf(sred[2], sred[3]));
    __syncthreads();

    float lsum = 0.f;
    for (int c = tid; c < NTOK; c += 128) {
        float e = expf(row[c] - bmax);
        row[c] = e;
        lsum += e;
    }
#pragma unroll
    for (int o = 16; o; o >>= 1) lsum += __shfl_xor_sync(0xffffffffu, lsum, o);
    if ((tid & 31) == 0) sred[tid >> 5] = lsum;
    __syncthreads();
    float inv = 1.0f / (sred[0] + sred[1] + sred[2] + sred[3]);
    for (int c = tid; c < NTOK; c += 128) row[c] *= inv;
    if (tid < SP - NTOK) row[NTOK + tid] = 0.0f;
}

// ---------------- Attention output: O_bh = P_bh @ V_bh ----------------
// grid (1, 10, 96); block 256; 64 rows x 64 cols per block; K tiled by 16 over padded SP.
__global__ __launch_bounds__(256) void attn_out_kernel(
    const float* __restrict__ S, const float* __restrict__ V, float* __restrict__ O)
{
    const int bh = blockIdx.z;
    const int b = bh / NHEAD, h = bh - b * NHEAD;
    const float* Sb = S + (size_t)bh * NTOK * SP;
    const float* Vb = V + (size_t)b * NTOK * DMODEL + h * HD;
    float* Ob = O + (size_t)b * NTOK * DMODEL + h * HD;
    const int m0 = blockIdx.y * 64;

    __shared__ float Ps[64][20];
    __shared__ float Vs[16][64];
    const int tid = threadIdx.x;
    const int ty = tid >> 4, tx = tid & 15;

    float acc[4][4] = {};
    for (int k0 = 0; k0 < SP; k0 += 16) {
        {   // P tile: 64 x 16
            int r  = tid >> 2;
            int k4 = (tid & 3) * 4;
            float4 p = make_float4(0.f, 0.f, 0.f, 0.f);
            if (m0 + r < NTOK) p = *(const float4*)(Sb + (size_t)(m0 + r) * SP + k0 + k4);
            *(float4*)&Ps[r][k4] = p;
        }
        {   // V tile: 16 x 64
            int kk = tid >> 4;
            int n4 = (tid & 15) * 4;
            float4 v = make_float4(0.f, 0.f, 0.f, 0.f);
            if (k0 + kk < NTOK) v = *(const float4*)(Vb + (size_t)(k0 + kk) * DMODEL + n4);
            *(float4*)&Vs[kk][n4] = v;
        }
        __syncthreads();
#pragma unroll
        for (int kk = 0; kk < 16; kk++) {
            float4 bv = *(const float4*)&Vs[kk][tx * 4];
            float a0 = Ps[ty * 4 + 0][kk];
            float a1 = Ps[ty * 4 + 1][kk];
            float a2 = Ps[ty * 4 + 2][kk];
            float a3 = Ps[ty * 4 + 3][kk];
            acc[0][0] += a0 * bv.x; acc[0][1] += a0 * bv.y; acc[0][2] += a0 * bv.z; acc[0][3] += a0 * bv.w;
            acc[1][0] += a1 * bv.x; acc[1][1] += a1 * bv.y; acc[1][2] += a1 * bv.z; acc[1][3] += a1 * bv.w;
            acc[2][0] += a2 * bv.x; acc[2][1] += a2 * bv.y; acc[2][2] += a2 * bv.z; acc[2][3] += a2 * bv.w;
            acc[3][0] += a3 * bv.x; acc[3][1] += a3 * bv.y; acc[3][2] += a3 * bv.z; acc[3][3] += a3 * bv.w;
        }
        __syncthreads();
    }
#pragma unroll
    for (int i = 0; i < 4; i++) {
        int m = m0 + ty * 4 + i;
        if (m >= NTOK) continue;
        float4 o4 = make_float4(acc[i][0], acc[i][1], acc[i][2], acc[i][3]);
        *(float4*)(Ob + (size_t)m * DMODEL + tx * 4) = o4;
    }
}

// ---------------- Classifier head (CLS token) ----------------
__global__ void head_kernel(const float* __restrict__ Hln, const float* __restrict__ W,
                            const float* __restrict__ bias, float* __restrict__ out)
{
    int idx = blockIdx.x * blockDim.x + threadIdx.x;
    if (idx >= BATCH * NCLS) return;
    int b = idx / NCLS, c = idx - b * NCLS;
    const float* hr = Hln + (size_t)b * NTOK * DMODEL;   // row 0 = CLS
    float s = bias[c];
#pragma unroll 4
    for (int d = 0; d < DMODEL; d++) s += hr[d] * W[(size_t)d * NCLS + c];
    out[idx] = s;
}

// ---------------- Host orchestration ----------------
extern "C" void kernel_launch(void* const* d_in, const int* in_sizes, int n_in,
                              void* d_out, int out_size)
{
    (void)in_sizes; (void)n_in; (void)out_size;
    const float* x      = (const float*)d_in[0];
    const float* proj_w = (const float*)d_in[1];
    const float* proj_b = (const float*)d_in[2];
    const float* cls_e  = (const float*)d_in[3];
    const float* pos_e  = (const float*)d_in[4];
    const float* ln1_g  = (const float*)d_in[5];
    const float* ln1_b  = (const float*)d_in[6];
    const float* qw     = (const float*)d_in[7];
    const float* qb     = (const float*)d_in[8];
    const float* kw     = (const float*)d_in[9];
    const float* kb     = (const float*)d_in[10];
    const float* vw     = (const float*)d_in[11];
    const float* vb     = (const float*)d_in[12];
    const float* ow     = (const float*)d_in[13];
    const float* ob     = (const float*)d_in[14];
    const float* ln2_g  = (const float*)d_in[15];
    const float* ln2_b  = (const float*)d_in[16];
    const float* fcw    = (const float*)d_in[17];
    const float* fcb    = (const float*)d_in[18];
    const float* pw     = (const float*)d_in[19];
    const float* pb     = (const float*)d_in[20];
    const float* lnf_g  = (const float*)d_in[21];
    const float* lnf_b  = (const float*)d_in[22];
    const float* head_w = (const float*)d_in[23];
    const float* head_b = (const float*)d_in[24];

    float *T, *E, *H, *Y, *Q, *Kp, *V, *O, *S, *Mm;
    cudaGetSymbolAddress((void**)&T,  g_T);
    cudaGetSymbolAddress((void**)&E,  g_E);
    cudaGetSymbolAddress((void**)&H,  g_H);
    cudaGetSymbolAddress((void**)&Y,  g_Y);
    cudaGetSymbolAddress((void**)&Q,  g_Q);
    cudaGetSymbolAddress((void**)&Kp, g_K);
    cudaGetSymbolAddress((void**)&V,  g_V);
    cudaGetSymbolAddress((void**)&O,  g_O);
    cudaGetSymbolAddress((void**)&S,  g_S);
    cudaGetSymbolAddress((void**)&Mm, g_M);

    // Patch embed
    patch_gather_kernel<<<(PROWS * DMODEL + 255) / 256, 256>>>(x, T);
    gemm_kernel<<<dim3(DMODEL / 128, PROWS / 128), 256>>>(
        T, proj_w, proj_b, (const float*)0, E, PROWS, DMODEL, DMODEL, 0);
    assemble_kernel<<<(TOKS * DMODEL + 255) / 256, 256>>>(E, cls_e, pos_e, H);

    const int MG = (TOKS + 127) / 128;   // 37
    for (int l = 0; l < LYRS; l++) {
        const size_t wo  = (size_t)l * DMODEL * DMODEL;
        const size_t bo  = (size_t)l * DMODEL;
        const size_t fwo = (size_t)l * DMODEL * MLPD;
        const size_t fbo = (size_t)l * MLPD;

        layernorm_kernel<<<TOKS, 256>>>(H, ln1_g + bo, ln1_b + bo, Y);
        gemm_kernel<<<dim3(6, MG), 256>>>(Y, qw + wo, qb + bo, (const float*)0, Q,  TOKS, DMODEL, DMODEL, 0);
        gemm_kernel<<<dim3(6, MG), 256>>>(Y, kw + wo, kb + bo, (const float*)0, Kp, TOKS, DMODEL, DMODEL, 0);
        gemm_kernel<<<dim3(6, MG), 256>>>(Y, vw + wo, vb + bo, (const float*)0, V,  TOKS, DMODEL, DMODEL, 0);

        attn_scores_kernel<<<dim3(10, 10, BATCH * NHEAD), 256>>>(Q, Kp, S);
        softmax_kernel<<<BATCH * NHEAD * NTOK, 128>>>(S);
        attn_out_kernel<<<dim3(1, 10, BATCH * NHEAD), 256>>>(S, V, O);

        gemm_kernel<<<dim3(6, MG), 256>>>(O, ow + wo, ob + bo, H, H, TOKS, DMODEL, DMODEL, 0);

        layernorm_kernel<<<TOKS, 256>>>(H, ln2_g + bo, ln2_b + bo, Y);
        gemm_kernel<<<dim3(MLPD / 128, MG), 256>>>(Y, fcw + fwo, fcb + fbo, (const float*)0, Mm, TOKS, MLPD, DMODEL, 1);
        gemm_kernel<<<dim3(6, MG), 256>>>(Mm, pw + fwo, pb + bo, H, H, TOKS, DMODEL, MLPD, 0);
    }

    layernorm_kernel<<<TOKS, 256>>>(H, lnf_g, lnf_b, Y);
    head_kernel<<<(BATCH * NCLS + 255) / 256, 256>>>(Y, head_w, head_b, (float*)d_out);
}

// round 13
// speedup vs baseline: 1.1969x; 1.1969x over previous
#include <cuda_runtime.h>
#include <math.h>

// ---------------- Config ----------------
#define BATCH 8
#define CCH   3
#define IMG   384
#define PCH   16
#define GH    24
#define GW    24
#define NP    576           // patches
#define NTOK  577           // +CLS
#define DMODEL 768
#define NHEAD 12
#define HD    64
#define LYRS  12
#define MLPD  3072
#define NCLS  1000

#define TOKS  (BATCH*NTOK)          // 4616
#define PROWS (BATCH*NP)            // 4608
#define SP    592                   // padded S row stride (577 -> 592, mult of 16)

typedef unsigned long long ull;

// ---------------- Scratch (static device globals; no runtime alloc) ----------------
__device__ float g_T[PROWS*DMODEL];      // gathered patch pixels
__device__ float g_E[PROWS*DMODEL];      // patch embeddings
__device__ float g_H[TOKS*DMODEL];       // residual stream
__device__ float g_Y[TOKS*DMODEL];       // LN output
__device__ float g_Q[TOKS*DMODEL];
__device__ float g_K[TOKS*DMODEL];
__device__ float g_V[TOKS*DMODEL];
__device__ float g_O[TOKS*DMODEL];
__device__ float g_S[(size_t)BATCH*NHEAD*NTOK*SP];   // attn probs (padded rows)
__device__ float g_M[(size_t)TOKS*MLPD];             // MLP hidden

__device__ __forceinline__ float gelu_exact(float x) {
    return 0.5f * x * (1.0f + erff(x * 0.70710678118654752f));
}

// ---------------- tf32 helpers ----------------
__device__ __forceinline__ unsigned f2tf(float f) {
    unsigned u;
    asm("cvt.rna.tf32.f32 %0, %1;" : "=r"(u) : "f"(f));
    return u;
}
// split x into hi (tf32) and lo (tf32 of remainder)
__device__ __forceinline__ void tfsplit(float x, unsigned& hi, unsigned& lo) {
    hi = f2tf(x);
    float h = __uint_as_float(hi);
    lo = f2tf(x - h);
}

#define MMA_TF32(d, a, b0v, b1v)                                               \
    asm volatile(                                                              \
        "mma.sync.aligned.m16n8k8.row.col.f32.tf32.tf32.f32 "                  \
        "{%0,%1,%2,%3},{%4,%5,%6,%7},{%8,%9},{%0,%1,%2,%3};"                   \
        : "+f"((d)[0]), "+f"((d)[1]), "+f"((d)[2]), "+f"((d)[3])               \
        : "r"((a)[0]), "r"((a)[1]), "r"((a)[2]), "r"((a)[3]),                  \
          "r"(b0v), "r"(b1v))

// ---------------- 3xTF32 tensor-core GEMM ----------------
// C = A[MxK] @ B[KxN] + bias (+gelu) (+res). BM=128, BN=128, BK=16.
// 256 threads = 8 warps (4 x 2), warp tile 32x64, m16n8k8 tf32 MMA,
// 3-way split (hi*hi + hi*lo + lo*hi) for fp32-grade accuracy.
// Requires: K % 16 == 0, N % 128 == 0. M guarded.
#define ASTRIDE 136   // padded SMEM row stride: c*136 mod 32 = c*8 -> conflict-free gathers
__global__ __launch_bounds__(256, 2) void gemm_tf32_kernel(
    const float* __restrict__ A, const float* __restrict__ B,
    const float* __restrict__ bias, const float* __restrict__ res,
    float* __restrict__ C, int M, int N, int K, int act)
{
    __shared__ float As[2][16][ASTRIDE];   // [buf][k][m]
    __shared__ float Bs[2][16][ASTRIDE];   // [buf][k][n]

    const int bm = blockIdx.y * 128;
    const int bn = blockIdx.x * 128;
    const int tid  = threadIdx.x;
    const int lane = tid & 31;
    const int w    = tid >> 5;
    const int warp_m = w & 3;        // 0..3 -> rows warp_m*32
    const int warp_n = w >> 2;       // 0..1 -> cols warp_n*64
    const int g = lane >> 2;         // 0..7
    const int c = lane & 3;          // 0..3

    float acc[2][8][4];
#pragma unroll
    for (int i = 0; i < 2; i++)
#pragma unroll
        for (int j = 0; j < 8; j++)
#pragma unroll
            for (int q = 0; q < 4; q++) acc[i][j][q] = 0.f;

    const int nt = K >> 4;

    // ---- prologue: tile 0 -> buf 0 ----
#pragma unroll
    for (int i = 0; i < 2; i++) {
        int f4 = tid + i * 256;
        int r  = f4 >> 2, kq = (f4 & 3) * 4;
        float4 va = make_float4(0.f, 0.f, 0.f, 0.f);
        if (bm + r < M) va = *(const float4*)(A + (size_t)(bm + r) * K + kq);
        As[0][kq + 0][r] = va.x; As[0][kq + 1][r] = va.y;
        As[0][kq + 2][r] = va.z; As[0][kq + 3][r] = va.w;
        int kk = f4 >> 5, nq = (f4 & 31) * 4;
        *(float4*)&Bs[0][kk][nq] = *(const float4*)(B + (size_t)kk * N + bn + nq);
    }
    __syncthreads();

    float4 ra[2], rb[2];
    for (int t = 0; t < nt; t++) {
        const int cur = t & 1;
        const bool more = (t + 1 < nt);
        if (more) {
            int k0 = (t + 1) << 4;
#pragma unroll
            for (int i = 0; i < 2; i++) {
                int f4 = tid + i * 256;
                int r  = f4 >> 2, kq = (f4 & 3) * 4;
                ra[i] = make_float4(0.f, 0.f, 0.f, 0.f);
                if (bm + r < M) ra[i] = *(const float4*)(A + (size_t)(bm + r) * K + k0 + kq);
                int kk = f4 >> 5, nq = (f4 & 31) * 4;
                rb[i] = *(const float4*)(B + (size_t)(k0 + kk) * N + bn + nq);
            }
        }

        // ---- compute on cur ----
#pragma unroll
        for (int k8 = 0; k8 < 2; k8++) {
            unsigned ah[2][4], al[2][4];
#pragma unroll
            for (int am = 0; am < 2; am++) {
                int mb = warp_m * 32 + am * 16;
                float v0 = As[cur][k8 * 8 + c    ][mb + g];
                float v1 = As[cur][k8 * 8 + c    ][mb + g + 8];
                float v2 = As[cur][k8 * 8 + c + 4][mb + g];
                float v3 = As[cur][k8 * 8 + c + 4][mb + g + 8];
                tfsplit(v0, ah[am][0], al[am][0]);
                tfsplit(v1, ah[am][1], al[am][1]);
                tfsplit(v2, ah[am][2], al[am][2]);
                tfsplit(v3, ah[am][3], al[am][3]);
            }
#pragma unroll
            for (int an = 0; an < 8; an++) {
                int nb = warp_n * 64 + an * 8 + g;
                float u0 = Bs[cur][k8 * 8 + c    ][nb];
                float u1 = Bs[cur][k8 * 8 + c + 4][nb];
                unsigned bh0, bl0, bh1, bl1;
                tfsplit(u0, bh0, bl0);
                tfsplit(u1, bh1, bl1);
#pragma unroll
                for (int am = 0; am < 2; am++) {
                    MMA_TF32(acc[am][an], ah[am], bh0, bh1);   // hi*hi
                    MMA_TF32(acc[am][an], ah[am], bl0, bl1);   // hi*lo
                    MMA_TF32(acc[am][an], al[am], bh0, bh1);   // lo*hi
                }
            }
        }

        if (more) {
            const int nxt = cur ^ 1;
#pragma unroll
            for (int i = 0; i < 2; i++) {
                int f4 = tid + i * 256;
                int r  = f4 >> 2, kq = (f4 & 3) * 4;
                As[nxt][kq + 0][r] = ra[i].x; As[nxt][kq + 1][r] = ra[i].y;
                As[nxt][kq + 2][r] = ra[i].z; As[nxt][kq + 3][r] = ra[i].w;
                int kk = f4 >> 5, nq = (f4 & 31) * 4;
                *(float4*)&Bs[nxt][kk][nq] = rb[i];
            }
        }
        __syncthreads();
    }

    // ---- epilogue ----
#pragma unroll
    for (int am = 0; am < 2; am++) {
        int row0 = bm + warp_m * 32 + am * 16 + g;
#pragma unroll
        for (int an = 0; an < 8; an++) {
            int col = bn + warp_n * 64 + an * 8 + c * 2;
            float b0 = bias[col], b1 = bias[col + 1];
#pragma unroll
            for (int half = 0; half < 2; half++) {
                int rr = row0 + half * 8;
                if (rr >= M) continue;
                float x0 = acc[am][an][half * 2 + 0] + b0;
                float x1 = acc[am][an][half * 2 + 1] + b1;
                if (act == 1) { x0 = gelu_exact(x0); x1 = gelu_exact(x1); }
                if (res) {
                    const float* rp = res + (size_t)rr * N + col;
                    x0 += rp[0]; x1 += rp[1];
                }
                float2 o = make_float2(x0, x1);
                *(float2*)(C + (size_t)rr * N + col) = o;
            }
        }
    }
}

// ---------------- Patch gather (faithful buggy flattening) ----------------
__global__ void patch_gather_kernel(const float* __restrict__ x, float* __restrict__ T)
{
    int idx = blockIdx.x * blockDim.x + threadIdx.x;
    if (idx >= PROWS * DMODEL) return;
    int p1  = idx / 221184;
    int rem = idx % 221184;
    int m   = rem >> 4;
    int p2  = rem & 15;
    int b   = m / 1728;
    int mm  = m - b * 1728;
    int c   = mm / 576;
    int mg  = mm - c * 576;
    int gh  = mg / 24;
    int gw  = mg - gh * 24;
    T[idx] = x[(((size_t)(b * CCH + c) * IMG) + gh * 16 + p1) * IMG + gw * 16 + p2];
}

// ---------------- Assemble tokens: CLS + patches + pos_emb ----------------
__global__ void assemble_kernel(const float* __restrict__ E, const float* __restrict__ cls,
                                const float* __restrict__ pos, float* __restrict__ H)
{
    int idx = blockIdx.x * blockDim.x + threadIdx.x;
    if (idx >= TOKS * DMODEL) return;
    int tok = idx / DMODEL;
    int k   = idx - tok * DMODEL;
    int b   = tok / NTOK;
    int n   = tok - b * NTOK;
    float v = (n == 0) ? cls[k] : E[((size_t)(b * NP + n - 1)) * DMODEL + k];
    H[idx] = v + pos[(size_t)n * DMODEL + k];
}

// ---------------- LayerNorm (row per block, 768 = 3*256) ----------------
__global__ void layernorm_kernel(const float* __restrict__ X, const float* __restrict__ g,
                                 const float* __restrict__ bta, float* __restrict__ Y)
{
    int r = blockIdx.x;
    const float* xr = X + (size_t)r * DMODEL;
    float* yr = Y + (size_t)r * DMODEL;
    int tid = threadIdx.x;
    float v0 = xr[tid], v1 = xr[tid + 256], v2 = xr[tid + 512];
    float s  = v0 + v1 + v2;
    float s2 = v0 * v0 + v1 * v1 + v2 * v2;
#pragma unroll
    for (int o = 16; o; o >>= 1) {
        s  += __shfl_xor_sync(0xffffffffu, s,  o);
        s2 += __shfl_xor_sync(0xffffffffu, s2, o);
    }
    __shared__ float r1[8], r2[8];
    if ((tid & 31) == 0) { r1[tid >> 5] = s; r2[tid >> 5] = s2; }
    __syncthreads();
    float S = 0.f, S2 = 0.f;
#pragma unroll
    for (int w = 0; w < 8; w++) { S += r1[w]; S2 += r2[w]; }
    float mean = S * (1.0f / 768.0f);
    float var  = S2 * (1.0f / 768.0f) - mean * mean;
    float inv  = rsqrtf(var + 1e-5f);
    yr[tid]       = (v0 - mean) * inv * g[tid]       + bta[tid];
    yr[tid + 256] = (v1 - mean) * inv * g[tid + 256] + bta[tid + 256];
    yr[tid + 512] = (v2 - mean) * inv * g[tid + 512] + bta[tid + 512];
}

// ---------------- Attention scores: S[bh] = scale * Q_bh @ K_bh^T ----------------
__global__ __launch_bounds__(256) void attn_scores_kernel(
    const float* __restrict__ Q, const float* __restrict__ K, float* __restrict__ S)
{
    const int bh = blockIdx.z;
    const int b = bh / NHEAD, h = bh - b * NHEAD;
    const float* Qb = Q + (size_t)b * NTOK * DMODEL + h * HD;
    const float* Kb = K + (size_t)b * NTOK * DMODEL + h * HD;
    float* Sb = S + (size_t)bh * NTOK * SP;
    const int m0 = blockIdx.y * 64, n0 = blockIdx.x * 64;

    __shared__ float Qs[64][68];
    __shared__ float Ks[64][68];
    const int tid = threadIdx.x;

#pragma unroll
    for (int i = 0; i < 4; i++) {
        int f4 = tid + i * 256;
        int r  = f4 >> 4;
        int d4 = (f4 & 15) * 4;
        float4 q = make_float4(0.f, 0.f, 0.f, 0.f), kv = q;
        if (m0 + r < NTOK) q  = *(const float4*)(Qb + (size_t)(m0 + r) * DMODEL + d4);
        if (n0 + r < NTOK) kv = *(const float4*)(Kb + (size_t)(n0 + r) * DMODEL + d4);
        *(float4*)&Qs[r][d4] = q;
        *(float4*)&Ks[r][d4] = kv;
    }
    __syncthreads();

    const int ty = tid >> 4, tx = tid & 15;
    float acc[4][4] = {};
#pragma unroll
    for (int d4 = 0; d4 < 16; d4++) {
        float4 a[4], bb[4];
#pragma unroll
        for (int i = 0; i < 4; i++) a[i]  = *(const float4*)&Qs[ty * 4 + i][d4 * 4];
#pragma unroll
        for (int j = 0; j < 4; j++) bb[j] = *(const float4*)&Ks[tx * 4 + j][d4 * 4];
#pragma unroll
        for (int i = 0; i < 4; i++)
#pragma unroll
            for (int j = 0; j < 4; j++)
                acc[i][j] += a[i].x * bb[j].x + a[i].y * bb[j].y
                           + a[i].z * bb[j].z + a[i].w * bb[j].w;
    }
    const float scale = 0.125f;  // 1/sqrt(64)
#pragma unroll
    for (int i = 0; i < 4; i++) {
        int m = m0 + ty * 4 + i;
        if (m >= NTOK) continue;
#pragma unroll
        for (int j = 0; j < 4; j++) {
            int n = n0 + tx * 4 + j;
            if (n < NTOK) Sb[(size_t)m * SP + n] = acc[i][j] * scale;
        }
    }
}

// ---------------- Row softmax over S (also zeroes pad cols 577..591) ----------------
__global__ void softmax_kernel(float* __restrict__ S)
{
    int r  = blockIdx.x;
    int bh = r / NTOK, m = r - bh * NTOK;
    float* row = S + (size_t)bh * NTOK * SP + (size_t)m * SP;
    int tid = threadIdx.x;                  // 128

    float lmax = -3.4e38f;
    for (int c = tid; c < NTOK; c += 128) lmax = fmaxf(lmax, row[c]);
#pragma unroll
    for (int o = 16; o; o >>= 1) lmax = fmaxf(lmax, __shfl_xor_sync(0xffffffffu, lmax, o));
    __shared__ float sred[4];
    if ((tid & 31) == 0) sred[tid >> 5] = lmax;
    __syncthreads();
    float bmax = fmaxf(fmaxf(sred[0], sred[1]), fmaxf(sred[2], sred[3]));
    __syncthreads();

    float lsum = 0.f;
    for (int c = tid; c < NTOK; c += 128) {
        float e = expf(row[c] - bmax);
        row[c] = e;
        lsum += e;
    }
#pragma unroll
    for (int o = 16; o; o >>= 1) lsum += __shfl_xor_sync(0xffffffffu, lsum, o);
    if ((tid & 31) == 0) sred[tid >> 5] = lsum;
    __syncthreads();
    float inv = 1.0f / (sred[0] + sred[1] + sred[2] + sred[3]);
    for (int c = tid; c < NTOK; c += 128) row[c] *= inv;
    if (tid < SP - NTOK) row[NTOK + tid] = 0.0f;
}

// ---------------- Attention output: O_bh = P_bh @ V_bh ----------------
__global__ __launch_bounds__(256) void attn_out_kernel(
    const float* __restrict__ S, const float* __restrict__ V, float* __restrict__ O)
{
    const int bh = blockIdx.z;
    const int b = bh / NHEAD, h = bh - b * NHEAD;
    const float* Sb = S + (size_t)bh * NTOK * SP;
    const float* Vb = V + (size_t)b * NTOK * DMODEL + h * HD;
    float* Ob = O + (size_t)b * NTOK * DMODEL + h * HD;
    const int m0 = blockIdx.y * 64;

    __shared__ float Ps[64][20];
    __shared__ float Vs[16][64];
    const int tid = threadIdx.x;
    const int ty = tid >> 4, tx = tid & 15;

    float acc[4][4] = {};
    for (int k0 = 0; k0 < SP; k0 += 16) {
        {
            int r  = tid >> 2;
            int k4 = (tid & 3) * 4;
            float4 p = make_float4(0.f, 0.f, 0.f, 0.f);
            if (m0 + r < NTOK) p = *(const float4*)(Sb + (size_t)(m0 + r) * SP + k0 + k4);
            *(float4*)&Ps[r][k4] = p;
        }
        {
            int kk = tid >> 4;
            int n4 = (tid & 15) * 4;
            float4 v = make_float4(0.f, 0.f, 0.f, 0.f);
            if (k0 + kk < NTOK) v = *(const float4*)(Vb + (size_t)(k0 + kk) * DMODEL + n4);
            *(float4*)&Vs[kk][n4] = v;
        }
        __syncthreads();
#pragma unroll
        for (int kk = 0; kk < 16; kk++) {
            float4 bv = *(const float4*)&Vs[kk][tx * 4];
            float a0 = Ps[ty * 4 + 0][kk];
            float a1 = Ps[ty * 4 + 1][kk];
            float a2 = Ps[ty * 4 + 2][kk];
            float a3 = Ps[ty * 4 + 3][kk];
            acc[0][0] += a0 * bv.x; acc[0][1] += a0 * bv.y; acc[0][2] += a0 * bv.z; acc[0][3] += a0 * bv.w;
            acc[1][0] += a1 * bv.x; acc[1][1] += a1 * bv.y; acc[1][2] += a1 * bv.z; acc[1][3] += a1 * bv.w;
            acc[2][0] += a2 * bv.x; acc[2][1] += a2 * bv.y; acc[2][2] += a2 * bv.z; acc[2][3] += a2 * bv.w;
            acc[3][0] += a3 * bv.x; acc[3][1] += a3 * bv.y; acc[3][2] += a3 * bv.z; acc[3][3] += a3 * bv.w;
        }
        __syncthreads();
    }
#pragma unroll
    for (int i = 0; i < 4; i++) {
        int m = m0 + ty * 4 + i;
        if (m >= NTOK) continue;
        float4 o4 = make_float4(acc[i][0], acc[i][1], acc[i][2], acc[i][3]);
        *(float4*)(Ob + (size_t)m * DMODEL + tx * 4) = o4;
    }
}

// ---------------- Classifier head (CLS token) ----------------
__global__ void head_kernel(const float* __restrict__ Hln, const float* __restrict__ W,
                            const float* __restrict__ bias, float* __restrict__ out)
{
    int idx = blockIdx.x * blockDim.x + threadIdx.x;
    if (idx >= BATCH * NCLS) return;
    int b = idx / NCLS, c = idx - b * NCLS;
    const float* hr = Hln + (size_t)b * NTOK * DMODEL;   // row 0 = CLS
    float s = bias[c];
#pragma unroll 4
    for (int d = 0; d < DMODEL; d++) s += hr[d] * W[(size_t)d * NCLS + c];
    out[idx] = s;
}

// ---------------- Host orchestration ----------------
extern "C" void kernel_launch(void* const* d_in, const int* in_sizes, int n_in,
                              void* d_out, int out_size)
{
    (void)in_sizes; (void)n_in; (void)out_size;
    const float* x      = (const float*)d_in[0];
    const float* proj_w = (const float*)d_in[1];
    const float* proj_b = (const float*)d_in[2];
    const float* cls_e  = (const float*)d_in[3];
    const float* pos_e  = (const float*)d_in[4];
    const float* ln1_g  = (const float*)d_in[5];
    const float* ln1_b  = (const float*)d_in[6];
    const float* qw     = (const float*)d_in[7];
    const float* qb     = (const float*)d_in[8];
    const float* kw     = (const float*)d_in[9];
    const float* kb     = (const float*)d_in[10];
    const float* vw     = (const float*)d_in[11];
    const float* vb     = (const float*)d_in[12];
    const float* ow     = (const float*)d_in[13];
    const float* ob     = (const float*)d_in[14];
    const float* ln2_g  = (const float*)d_in[15];
    const float* ln2_b  = (const float*)d_in[16];
    const float* fcw    = (const float*)d_in[17];
    const float* fcb    = (const float*)d_in[18];
    const float* pw     = (const float*)d_in[19];
    const float* pb     = (const float*)d_in[20];
    const float* lnf_g  = (const float*)d_in[21];
    const float* lnf_b  = (const float*)d_in[22];
    const float* head_w = (const float*)d_in[23];
    const float* head_b = (const float*)d_in[24];

    float *T, *E, *H, *Y, *Q, *Kp, *V, *O, *S, *Mm;
    cudaGetSymbolAddress((void**)&T,  g_T);
    cudaGetSymbolAddress((void**)&E,  g_E);
    cudaGetSymbolAddress((void**)&H,  g_H);
    cudaGetSymbolAddress((void**)&Y,  g_Y);
    cudaGetSymbolAddress((void**)&Q,  g_Q);
    cudaGetSymbolAddress((void**)&Kp, g_K);
    cudaGetSymbolAddress((void**)&V,  g_V);
    cudaGetSymbolAddress((void**)&O,  g_O);
    cudaGetSymbolAddress((void**)&S,  g_S);
    cudaGetSymbolAddress((void**)&Mm, g_M);

    // Patch embed
    patch_gather_kernel<<<(PROWS * DMODEL + 255) / 256, 256>>>(x, T);
    gemm_tf32_kernel<<<dim3(DMODEL / 128, PROWS / 128), 256>>>(
        T, proj_w, proj_b, (const float*)0, E, PROWS, DMODEL, DMODEL, 0);
    assemble_kernel<<<(TOKS * DMODEL + 255) / 256, 256>>>(E, cls_e, pos_e, H);

    const int MG = (TOKS + 127) / 128;   // 37
    for (int l = 0; l < LYRS; l++) {
        const size_t wo  = (size_t)l * DMODEL * DMODEL;
        const size_t bo  = (size_t)l * DMODEL;
        const size_t fwo = (size_t)l * DMODEL * MLPD;
        const size_t fbo = (size_t)l * MLPD;

        layernorm_kernel<<<TOKS, 256>>>(H, ln1_g + bo, ln1_b + bo, Y);
        gemm_tf32_kernel<<<dim3(6, MG), 256>>>(Y, qw + wo, qb + bo, (const float*)0, Q,  TOKS, DMODEL, DMODEL, 0);
        gemm_tf32_kernel<<<dim3(6, MG), 256>>>(Y, kw + wo, kb + bo, (const float*)0, Kp, TOKS, DMODEL, DMODEL, 0);
        gemm_tf32_kernel<<<dim3(6, MG), 256>>>(Y, vw + wo, vb + bo, (const float*)0, V,  TOKS, DMODEL, DMODEL, 0);

        attn_scores_kernel<<<dim3(10, 10, BATCH * NHEAD), 256>>>(Q, Kp, S);
        softmax_kernel<<<BATCH * NHEAD * NTOK, 128>>>(S);
        attn_out_kernel<<<dim3(1, 10, BATCH * NHEAD), 256>>>(S, V, O);

        gemm_tf32_kernel<<<dim3(6, MG), 256>>>(O, ow + wo, ob + bo, H, H, TOKS, DMODEL, DMODEL, 0);

        layernorm_kernel<<<TOKS, 256>>>(H, ln2_g + bo, ln2_b + bo, Y);
        gemm_tf32_kernel<<<dim3(MLPD / 128, MG), 256>>>(Y, fcw + fwo, fcb + fbo, (const float*)0, Mm, TOKS, MLPD, DMODEL, 1);
        gemm_tf32_kernel<<<dim3(6, MG), 256>>>(Mm, pw + fwo, pb + bo, H, H, TOKS, DMODEL, MLPD, 0);
    }

    layernorm_kernel<<<TOKS, 256>>>(H, lnf_g, lnf_b, Y);
    head_kernel<<<(BATCH * NCLS + 255) / 256, 256>>>(Y, head_w, head_b, (float*)d_out);
}

// round 15
// speedup vs baseline: 1.8447x; 1.5413x over previous
#include <cuda_runtime.h>
#include <cuda_fp16.h>
#include <math.h>
#include <stdint.h>

// ---------------- Config ----------------
#define BATCH 8
#define CCH   3
#define IMG   384
#define NP    576
#define NTOK  577
#define DMODEL 768
#define NHEAD 12
#define HD    64
#define LYRS  12
#define MLPD  3072
#define NCLS  1000

#define TOKS   (BATCH*NTOK)      // 4616
#define TOKS_P 4736              // 37*128
#define PROWS  (BATCH*NP)        // 4608
#define SP     592
#define QSTR   2304              // fused QKV row stride

// Weight split buffer offsets (elements). Layout per matrix: [N][K] half.
#define W_PATCH_OFF 0
#define W_PATCH_SZ  (768*768)
#define W_LAYER_SZ  (2304*768 + 768*768 + 3072*768 + 768*3072)
#define W_QKV_OFF   0
#define W_O_OFF     (2304*768)
#define W_FC_OFF    (W_O_OFF + 768*768)
#define W_PW_OFF    (W_FC_OFF + 3072*768)
#define W_TOTAL     (W_PATCH_SZ + 12*W_LAYER_SZ)

// ---------------- Scratch (static device globals; zero-initialized) ----------------
__device__ __align__(256) __half g_Wh[W_TOTAL];
__device__ __align__(256) __half g_Wl[W_TOTAL];
__device__ __align__(256) __half g_Th[PROWS*DMODEL];
__device__ __align__(256) __half g_Tl[PROWS*DMODEL];
__device__ __align__(256) __half g_Yh[TOKS_P*DMODEL];
__device__ __align__(256) __half g_Yl[TOKS_P*DMODEL];
__device__ __align__(256) __half g_Oh[TOKS_P*DMODEL];
__device__ __align__(256) __half g_Ol[TOKS_P*DMODEL];
__device__ __align__(256) __half g_Mh[(size_t)TOKS_P*MLPD];
__device__ __align__(256) __half g_Ml[(size_t)TOKS_P*MLPD];
__device__ float g_E[PROWS*DMODEL];
__device__ float g_H[TOKS*DMODEL];
__device__ float g_Y[TOKS*DMODEL];
__device__ float g_QKV[(size_t)TOKS*QSTR];
__device__ float g_S[(size_t)BATCH*NHEAD*NTOK*SP];
__device__ float g_qkvb[LYRS*QSTR];

// ---------------- helpers ----------------
__device__ __forceinline__ uint32_t smem_u32(const void* p) {
    uint32_t a;
    asm("{ .reg .u64 t; cvta.to.shared.u64 t, %1; cvt.u32.u64 %0, t; }" : "=r"(a) : "l"(p));
    return a;
}
__device__ __forceinline__ float gelu_exact(float x) {
    return 0.5f * x * (1.0f + erff(x * 0.70710678118654752f));
}
__device__ __forceinline__ void hsplit(float x, __half& h, __half& l) {
    h = __float2half_rn(x);
    l = __float2half_rn(x - __half2float(h));
}

#define LDSM_X4(r0, r1, r2, r3, addr)                                          \
    asm volatile("ldmatrix.sync.aligned.m8n8.x4.shared.b16 {%0,%1,%2,%3}, [%4];" \
                 : "=r"(r0), "=r"(r1), "=r"(r2), "=r"(r3) : "r"(addr))

#define MMA16816(d, a0, a1, a2, a3, b0, b1)                                    \
    asm volatile("mma.sync.aligned.m16n8k16.row.col.f32.f16.f16.f32 "          \
                 "{%0,%1,%2,%3},{%4,%5,%6,%7},{%8,%9},{%0,%1,%2,%3};"          \
                 : "+f"((d)[0]), "+f"((d)[1]), "+f"((d)[2]), "+f"((d)[3])      \
                 : "r"(a0), "r"(a1), "r"(a2), "r"(a3), "r"(b0), "r"(b1))

// ---------------- fp16-split HMMA GEMM ----------------
// C = A @ W^T + bias.  A:[Mpad][K] half hi/lo, W:[N][K] half hi/lo.
// 3 passes: Ah*Wh + Ah*Wl + Al*Wh  (fp32 accum) -> fp32-grade accuracy.
// mode 0: Cf = v+bias; 1: Cf = v+bias+Cf(res); 2: gelu(v+bias) split -> Ch/Cl.
// BM=128, BN=128, BK=32, 256 threads (8 warps: 4M x 2N), warp tile 32x64.
#define ASTR 40    // SMEM row stride in halves (80B): conflict-free ldmatrix & stores

__global__ __launch_bounds__(256, 1) void gemm_h_kernel(
    const __half* __restrict__ Ah, const __half* __restrict__ Al,
    const __half* __restrict__ Wh, const __half* __restrict__ Wl,
    const float* __restrict__ bias, float* Cf,
    __half* __restrict__ Ch, __half* __restrict__ Cl,
    int M, int N, int K, int mode)
{
    __shared__ __half sAh[128 * ASTR];
    __shared__ __half sAl[128 * ASTR];
    __shared__ __half sBh[128 * ASTR];
    __shared__ __half sBl[128 * ASTR];

    const int tid  = threadIdx.x;
    const int lane = tid & 31;
    const int w    = tid >> 5;
    const int wm   = w & 3;          // warp M index (rows wm*32)
    const int wn   = w >> 2;         // warp N index (cols wn*64)
    const int bm = blockIdx.y * 128;
    const int bn = blockIdx.x * 128;

    const uint32_t uAh = smem_u32(sAh), uAl = smem_u32(sAl);
    const uint32_t uBh = smem_u32(sBh), uBl = smem_u32(sBl);

    // per-thread load mapping: idx in 0..511 (2 per thread), row=idx>>2, kq=(idx&3)*8
    const int lr0 = tid >> 2,          lk0 = (tid & 3) * 8;
    const int lr1 = (tid + 256) >> 2,  lk1 = lk0;

    // ldmatrix address components (per thread)
    const int arow = wm * 32 + (lane & 15);
    const int acol = (lane >> 4) * 8;
    const int brow_base = wn * 64 + (lane & 7) + ((lane >> 4) << 3);
    const int bcol = (lane & 8);

    float acc[2][8][4];
#pragma unroll
    for (int i = 0; i < 2; i++)
#pragma unroll
        for (int j = 0; j < 8; j++)
#pragma unroll
            for (int q = 0; q < 4; q++) acc[i][j][q] = 0.f;

    const int nt = K >> 5;
    float4 rAh0, rAh1, rAl0, rAl1, rBh0, rBh1, rBl0, rBl1;

    // prologue load t=0
    {
        const __half* a = Ah; const __half* al = Al;
        rAh0 = *(const float4*)(a  + (size_t)(bm + lr0) * K + lk0);
        rAh1 = *(const float4*)(a  + (size_t)(bm + lr1) * K + lk1);
        rAl0 = *(const float4*)(al + (size_t)(bm + lr0) * K + lk0);
        rAl1 = *(const float4*)(al + (size_t)(bm + lr1) * K + lk1);
        rBh0 = *(const float4*)(Wh + (size_t)(bn + lr0) * K + lk0);
        rBh1 = *(const float4*)(Wh + (size_t)(bn + lr1) * K + lk1);
        rBl0 = *(const float4*)(Wl + (size_t)(bn + lr0) * K + lk0);
        rBl1 = *(const float4*)(Wl + (size_t)(bn + lr1) * K + lk1);
    }
    *(float4*)&sAh[lr0 * ASTR + lk0] = rAh0; *(float4*)&sAh[lr1 * ASTR + lk1] = rAh1;
    *(float4*)&sAl[lr0 * ASTR + lk0] = rAl0; *(float4*)&sAl[lr1 * ASTR + lk1] = rAl1;
    *(float4*)&sBh[lr0 * ASTR + lk0] = rBh0; *(float4*)&sBh[lr1 * ASTR + lk1] = rBh1;
    *(float4*)&sBl[lr0 * ASTR + lk0] = rBl0; *(float4*)&sBl[lr1 * ASTR + lk1] = rBl1;
    __syncthreads();

    for (int t = 0; t < nt; t++) {
        const bool more = (t + 1 < nt);
        if (more) {
            const int k0 = (t + 1) << 5;
            rAh0 = *(const float4*)(Ah + (size_t)(bm + lr0) * K + k0 + lk0);
            rAh1 = *(const float4*)(Ah + (size_t)(bm + lr1) * K + k0 + lk1);
            rAl0 = *(const float4*)(Al + (size_t)(bm + lr0) * K + k0 + lk0);
            rAl1 = *(const float4*)(Al + (size_t)(bm + lr1) * K + k0 + lk1);
            rBh0 = *(const float4*)(Wh + (size_t)(bn + lr0) * K + k0 + lk0);
            rBh1 = *(const float4*)(Wh + (size_t)(bn + lr1) * K + k0 + lk1);
            rBl0 = *(const float4*)(Wl + (size_t)(bn + lr0) * K + k0 + lk0);
            rBl1 = *(const float4*)(Wl + (size_t)(bn + lr1) * K + k0 + lk1);
        }

#pragma unroll
        for (int k16 = 0; k16 < 2; k16++) {
            const int kc = k16 * 16;
            uint32_t ah[2][4], al2[2][4];
#pragma unroll
            for (int am = 0; am < 2; am++) {
                uint32_t off = ((arow + am * 16) * ASTR + kc + acol) * 2;
                LDSM_X4(ah[am][0], ah[am][1], ah[am][2], ah[am][3], uAh + off);
                LDSM_X4(al2[am][0], al2[am][1], al2[am][2], al2[am][3], uAl + off);
            }
            uint32_t bh[4][4], bl[4][4];
#pragma unroll
            for (int j = 0; j < 4; j++) {
                uint32_t off = ((brow_base + j * 16) * ASTR + kc + bcol) * 2;
                LDSM_X4(bh[j][0], bh[j][1], bh[j][2], bh[j][3], uBh + off);
                LDSM_X4(bl[j][0], bl[j][1], bl[j][2], bl[j][3], uBl + off);
            }
#pragma unroll
            for (int am = 0; am < 2; am++) {
#pragma unroll
                for (int jj = 0; jj < 8; jj++) {
                    const int jx = jj >> 1, sel = (jj & 1) * 2;
                    MMA16816(acc[am][jj], ah[am][0], ah[am][1], ah[am][2], ah[am][3],
                             bh[jx][sel], bh[jx][sel + 1]);
                    MMA16816(acc[am][jj], ah[am][0], ah[am][1], ah[am][2], ah[am][3],
                             bl[jx][sel], bl[jx][sel + 1]);
                    MMA16816(acc[am][jj], al2[am][0], al2[am][1], al2[am][2], al2[am][3],
                             bh[jx][sel], bh[jx][sel + 1]);
                }
            }
        }

        if (more) {
            __syncthreads();
            *(float4*)&sAh[lr0 * ASTR + lk0] = rAh0; *(float4*)&sAh[lr1 * ASTR + lk1] = rAh1;
            *(float4*)&sAl[lr0 * ASTR + lk0] = rAl0; *(float4*)&sAl[lr1 * ASTR + lk1] = rAl1;
            *(float4*)&sBh[lr0 * ASTR + lk0] = rBh0; *(float4*)&sBh[lr1 * ASTR + lk1] = rBh1;
            *(float4*)&sBl[lr0 * ASTR + lk0] = rBl0; *(float4*)&sBl[lr1 * ASTR + lk1] = rBl1;
            __syncthreads();
        }
    }

    // ---- epilogue ----
    const int gRow0 = bm + wm * 32 + (lane >> 2);
    const int gCol0 = bn + wn * 64 + (lane & 3) * 2;
#pragma unroll
    for (int am = 0; am < 2; am++) {
#pragma unroll
        for (int jj = 0; jj < 8; jj++) {
            const int gc = gCol0 + jj * 8;
            const float2 b2 = *(const float2*)(bias + gc);
#pragma unroll
            for (int hrow = 0; hrow < 2; hrow++) {
                const int gr = gRow0 + am * 16 + hrow * 8;
                if (gr >= M) continue;
                float x0 = acc[am][jj][hrow * 2 + 0] + b2.x;
                float x1 = acc[am][jj][hrow * 2 + 1] + b2.y;
                if (mode <= 1) {
                    if (mode == 1) {
                        float2 rv = *(const float2*)(Cf + (size_t)gr * N + gc);
                        x0 += rv.x; x1 += rv.y;
                    }
                    *(float2*)(Cf + (size_t)gr * N + gc) = make_float2(x0, x1);
                } else {
                    x0 = gelu_exact(x0); x1 = gelu_exact(x1);
                    __half h0, l0, h1, l1;
                    hsplit(x0, h0, l0); hsplit(x1, h1, l1);
                    *(__half2*)(Ch + (size_t)gr * N + gc) = __halves2half2(h0, h1);
                    *(__half2*)(Cl + (size_t)gr * N + gc) = __halves2half2(l0, l1);
                }
            }
        }
    }
}

// ---------------- Weight transpose + split: src[K][N] f32 -> dst[N][K] half hi/lo ----------------
__global__ void transp_split_kernel(const float* __restrict__ src,
                                    __half* __restrict__ dh,
                                    __half* __restrict__ dl, int K, int N)
{
    __shared__ float t[32][33];
    int k0 = blockIdx.y * 32, n0 = blockIdx.x * 32;
    int tx = threadIdx.x, ty = threadIdx.y;   // (32, 8)
#pragma unroll
    for (int j = 0; j < 4; j++)
        t[ty + j * 8][tx] = src[(size_t)(k0 + ty + j * 8) * N + n0 + tx];
    __syncthreads();
#pragma unroll
    for (int j = 0; j < 4; j++) {
        int n = n0 + ty + j * 8;
        float v = t[tx][ty + j * 8];
        __half h, l; hsplit(v, h, l);
        dh[(size_t)n * K + k0 + tx] = h;
        dl[(size_t)n * K + k0 + tx] = l;
    }
}

// ---------------- QKV bias pack ----------------
__global__ void biaspack_kernel(const float* qb, const float* kb, const float* vb, float* out)
{
    int idx = blockIdx.x * blockDim.x + threadIdx.x;
    if (idx >= LYRS * QSTR) return;
    int l = idx / QSTR, c = idx - l * QSTR;
    float v = (c < 768) ? qb[l * 768 + c] : (c < 1536) ? kb[l * 768 + c - 768] : vb[l * 768 + c - 1536];
    out[idx] = v;
}

// ---------------- Patch gather (faithful buggy flattening) + split ----------------
__global__ void patch_gather_kernel(const float* __restrict__ x,
                                    __half* __restrict__ Th, __half* __restrict__ Tl)
{
    int idx = blockIdx.x * blockDim.x + threadIdx.x;
    if (idx >= PROWS * DMODEL) return;
    int p1  = idx / 221184;
    int rem = idx % 221184;
    int m   = rem >> 4;
    int p2  = rem & 15;
    int b   = m / 1728;
    int mm  = m - b * 1728;
    int c   = mm / 576;
    int mg  = mm - c * 576;
    int gh  = mg / 24;
    int gw  = mg - gh * 24;
    float v = x[(((size_t)(b * CCH + c) * IMG) + gh * 16 + p1) * IMG + gw * 16 + p2];
    __half h, l; hsplit(v, h, l);
    Th[idx] = h; Tl[idx] = l;
}

// ---------------- Assemble tokens ----------------
__global__ void assemble_kernel(const float* __restrict__ E, const float* __restrict__ cls,
                                const float* __restrict__ pos, float* __restrict__ H)
{
    int idx = blockIdx.x * blockDim.x + threadIdx.x;
    if (idx >= TOKS * DMODEL) return;
    int tok = idx / DMODEL;
    int k   = idx - tok * DMODEL;
    int b   = tok / NTOK;
    int n   = tok - b * NTOK;
    float v = (n == 0) ? cls[k] : E[((size_t)(b * NP + n - 1)) * DMODEL + k];
    H[idx] = v + pos[(size_t)n * DMODEL + k];
}

// ---------------- LayerNorm: split output (GEMM A operand) ----------------
__global__ void ln_split_kernel(const float* __restrict__ X, const float* __restrict__ g,
                                const float* __restrict__ bta,
                                __half* __restrict__ Yh, __half* __restrict__ Yl)
{
    int r = blockIdx.x;
    const float* xr = X + (size_t)r * DMODEL;
    int tid = threadIdx.x;
    float v0 = xr[tid], v1 = xr[tid + 256], v2 = xr[tid + 512];
    float s  = v0 + v1 + v2;
    float s2 = v0 * v0 + v1 * v1 + v2 * v2;
#pragma unroll
    for (int o = 16; o; o >>= 1) {
        s  += __shfl_xor_sync(0xffffffffu, s,  o);
        s2 += __shfl_xor_sync(0xffffffffu, s2, o);
    }
    __shared__ float r1[8], r2[8];
    if ((tid & 31) == 0) { r1[tid >> 5] = s; r2[tid >> 5] = s2; }
    __syncthreads();
    float S = 0.f, S2 = 0.f;
#pragma unroll
    for (int ww = 0; ww < 8; ww++) { S += r1[ww]; S2 += r2[ww]; }
    float mean = S * (1.0f / 768.0f);
    float var  = S2 * (1.0f / 768.0f) - mean * mean;
    float inv  = rsqrtf(var + 1e-5f);
#pragma unroll
    for (int j = 0; j < 3; j++) {
        int c = tid + j * 256;
        float y = (xr[c] - mean) * inv * g[c] + bta[c];
        __half h, l; hsplit(y, h, l);
        Yh[(size_t)r * DMODEL + c] = h;
        Yl[(size_t)r * DMODEL + c] = l;
    }
}

// ---------------- LayerNorm fp32 out (final) ----------------
__global__ void layernorm_kernel(const float* __restrict__ X, const float* __restrict__ g,
                                 const float* __restrict__ bta, float* __restrict__ Y)
{
    int r = blockIdx.x;
    const float* xr = X + (size_t)r * DMODEL;
    float* yr = Y + (size_t)r * DMODEL;
    int tid = threadIdx.x;
    float v0 = xr[tid], v1 = xr[tid + 256], v2 = xr[tid + 512];
    float s  = v0 + v1 + v2;
    float s2 = v0 * v0 + v1 * v1 + v2 * v2;
#pragma unroll
    for (int o = 16; o; o >>= 1) {
        s  += __shfl_xor_sync(0xffffffffu, s,  o);
        s2 += __shfl_xor_sync(0xffffffffu, s2, o);
    }
    __shared__ float r1[8], r2[8];
    if ((tid & 31) == 0) { r1[tid >> 5] = s; r2[tid >> 5] = s2; }
    __syncthreads();
    float S = 0.f, S2 = 0.f;
#pragma unroll
    for (int ww = 0; ww < 8; ww++) { S += r1[ww]; S2 += r2[ww]; }
    float mean = S * (1.0f / 768.0f);
    float var  = S2 * (1.0f / 768.0f) - mean * mean;
    float inv  = rsqrtf(var + 1e-5f);
    yr[tid]       = (v0 - mean) * inv * g[tid]       + bta[tid];
    yr[tid + 256] = (v1 - mean) * inv * g[tid + 256] + bta[tid + 256];
    yr[tid + 512] = (v2 - mean) * inv * g[tid + 512] + bta[tid + 512];
}

// ---------------- Attention scores (fused QKV, stride 2304) ----------------
__global__ __launch_bounds__(256) void attn_scores_kernel(
    const float* __restrict__ QKV, float* __restrict__ S)
{
    const int bh = blockIdx.z;
    const int b = bh / NHEAD, h = bh - b * NHEAD;
    const float* Qb = QKV + (size_t)b * NTOK * QSTR + h * HD;
    const float* Kb = QKV + (size_t)b * NTOK * QSTR + 768 + h * HD;
    float* Sb = S + (size_t)bh * NTOK * SP;
    const int m0 = blockIdx.y * 64, n0 = blockIdx.x * 64;

    __shared__ float Qs[64][68];
    __shared__ float Ks[64][68];
    const int tid = threadIdx.x;

#pragma unroll
    for (int i = 0; i < 4; i++) {
        int f4 = tid + i * 256;
        int r  = f4 >> 4;
        int d4 = (f4 & 15) * 4;
        float4 q = make_float4(0.f, 0.f, 0.f, 0.f), kv = q;
        if (m0 + r < NTOK) q  = *(const float4*)(Qb + (size_t)(m0 + r) * QSTR + d4);
        if (n0 + r < NTOK) kv = *(const float4*)(Kb + (size_t)(n0 + r) * QSTR + d4);
        *(float4*)&Qs[r][d4] = q;
        *(float4*)&Ks[r][d4] = kv;
    }
    __syncthreads();

    const int ty = tid >> 4, tx = tid & 15;
    float acc[4][4] = {};
#pragma unroll
    for (int d4 = 0; d4 < 16; d4++) {
        float4 a[4], bb[4];
#pragma unroll
        for (int i = 0; i < 4; i++) a[i]  = *(const float4*)&Qs[ty * 4 + i][d4 * 4];
#pragma unroll
        for (int j = 0; j < 4; j++) bb[j] = *(const float4*)&Ks[tx * 4 + j][d4 * 4];
#pragma unroll
        for (int i = 0; i < 4; i++)
#pragma unroll
            for (int j = 0; j < 4; j++)
                acc[i][j] += a[i].x * bb[j].x + a[i].y * bb[j].y
                           + a[i].z * bb[j].z + a[i].w * bb[j].w;
    }
    const float scale = 0.125f;
#pragma unroll
    for (int i = 0; i < 4; i++) {
        int m = m0 + ty * 4 + i;
        if (m >= NTOK) continue;
#pragma unroll
        for (int j = 0; j < 4; j++) {
            int n = n0 + tx * 4 + j;
            if (n < NTOK) Sb[(size_t)m * SP + n] = acc[i][j] * scale;
        }
    }
}

// ---------------- Softmax ----------------
__global__ void softmax_kernel(float* __restrict__ S)
{
    int r  = blockIdx.x;
    int bh = r / NTOK, m = r - bh * NTOK;
    float* row = S + (size_t)bh * NTOK * SP + (size_t)m * SP;
    int tid = threadIdx.x;

    float lmax = -3.4e38f;
    for (int c = tid; c < NTOK; c += 128) lmax = fmaxf(lmax, row[c]);
#pragma unroll
    for (int o = 16; o; o >>= 1) lmax = fmaxf(lmax, __shfl_xor_sync(0xffffffffu, lmax, o));
    __shared__ float sred[4];
    if ((tid & 31) == 0) sred[tid >> 5] = lmax;
    __syncthreads();
    float bmax = fmaxf(fmaxf(sred[0], sred[1]), fmaxf(sred[2], sred[3]));
    __syncthreads();

    float lsum = 0.f;
    for (int c = tid; c < NTOK; c += 128) {
        float e = expf(row[c] - bmax);
        row[c] = e;
        lsum += e;
    }
#pragma unroll
    for (int o = 16; o; o >>= 1) lsum += __shfl_xor_sync(0xffffffffu, lsum, o);
    if ((tid & 31) == 0) sred[tid >> 5] = lsum;
    __syncthreads();
    float inv = 1.0f / (sred[0] + sred[1] + sred[2] + sred[3]);
    for (int c = tid; c < NTOK; c += 128) row[c] *= inv;
    if (tid < SP - NTOK) row[NTOK + tid] = 0.0f;
}

// ---------------- Attention output: P @ V -> split half ----------------
__global__ __launch_bounds__(256) void attn_out_kernel(
    const float* __restrict__ S, const float* __restrict__ QKV,
    __half* __restrict__ Oh, __half* __restrict__ Ol)
{
    const int bh = blockIdx.z;
    const int b = bh / NHEAD, h = bh - b * NHEAD;
    const float* Sb = S + (size_t)bh * NTOK * SP;
    const float* Vb = QKV + (size_t)b * NTOK * QSTR + 1536 + h * HD;
    const int m0 = blockIdx.y * 64;

    __shared__ float Ps[64][20];
    __shared__ float Vs[16][64];
    const int tid = threadIdx.x;
    const int ty = tid >> 4, tx = tid & 15;

    float acc[4][4] = {};
    for (int k0 = 0; k0 < SP; k0 += 16) {
        {
            int r  = tid >> 2;
            int k4 = (tid & 3) * 4;
            float4 p = make_float4(0.f, 0.f, 0.f, 0.f);
            if (m0 + r < NTOK) p = *(const float4*)(Sb + (size_t)(m0 + r) * SP + k0 + k4);
            *(float4*)&Ps[r][k4] = p;
        }
        {
            int kk = tid >> 4;
            int n4 = (tid & 15) * 4;
            float4 v = make_float4(0.f, 0.f, 0.f, 0.f);
            if (k0 + kk < NTOK) v = *(const float4*)(Vb + (size_t)(k0 + kk) * QSTR + n4);
            *(float4*)&Vs[kk][n4] = v;
        }
        __syncthreads();
#pragma unroll
        for (int kk = 0; kk < 16; kk++) {
            float4 bv = *(const float4*)&Vs[kk][tx * 4];
            float a0 = Ps[ty * 4 + 0][kk];
            float a1 = Ps[ty * 4 + 1][kk];
            float a2 = Ps[ty * 4 + 2][kk];
            float a3 = Ps[ty * 4 + 3][kk];
            acc[0][0] += a0 * bv.x; acc[0][1] += a0 * bv.y; acc[0][2] += a0 * bv.z; acc[0][3] += a0 * bv.w;
            acc[1][0] += a1 * bv.x; acc[1][1] += a1 * bv.y; acc[1][2] += a1 * bv.z; acc[1][3] += a1 * bv.w;
            acc[2][0] += a2 * bv.x; acc[2][1] += a2 * bv.y; acc[2][2] += a2 * bv.z; acc[2][3] += a2 * bv.w;
            acc[3][0] += a3 * bv.x; acc[3][1] += a3 * bv.y; acc[3][2] += a3 * bv.z; acc[3][3] += a3 * bv.w;
        }
        __syncthreads();
    }
#pragma unroll
    for (int i = 0; i < 4; i++) {
        int m = m0 + ty * 4 + i;
        if (m >= NTOK) continue;
        size_t base = ((size_t)(b * NTOK + m)) * DMODEL + h * HD + tx * 4;
        __half h0, l0, h1, l1, h2, l2, h3, l3;
        hsplit(acc[i][0], h0, l0); hsplit(acc[i][1], h1, l1);
        hsplit(acc[i][2], h2, l2); hsplit(acc[i][3], h3, l3);
        __half2* ph = (__half2*)(Oh + base);
        __half2* pl = (__half2*)(Ol + base);
        ph[0] = __halves2half2(h0, h1); ph[1] = __halves2half2(h2, h3);
        pl[0] = __halves2half2(l0, l1); pl[1] = __halves2half2(l2, l3);
    }
}

// ---------------- Classifier head ----------------
__global__ void head_kernel(const float* __restrict__ Hln, const float* __restrict__ W,
                            const float* __restrict__ bias, float* __restrict__ out)
{
    int idx = blockIdx.x * blockDim.x + threadIdx.x;
    if (idx >= BATCH * NCLS) return;
    int b = idx / NCLS, c = idx - b * NCLS;
    const float* hr = Hln + (size_t)b * NTOK * DMODEL;
    float s = bias[c];
#pragma unroll 4
    for (int d = 0; d < DMODEL; d++) s += hr[d] * W[(size_t)d * NCLS + c];
    out[idx] = s;
}

// ---------------- Host orchestration ----------------
extern "C" void kernel_launch(void* const* d_in, const int* in_sizes, int n_in,
                              void* d_out, int out_size)
{
    (void)in_sizes; (void)n_in; (void)out_size;
    const float* x      = (const float*)d_in[0];
    const float* proj_w = (const float*)d_in[1];
    const float* proj_b = (const float*)d_in[2];
    const float* cls_e  = (const float*)d_in[3];
    const float* pos_e  = (const float*)d_in[4];
    const float* ln1_g  = (const float*)d_in[5];
    const float* ln1_b  = (const float*)d_in[6];
    const float* qw     = (const float*)d_in[7];
    const float* qb     = (const float*)d_in[8];
    const float* kw     = (const float*)d_in[9];
    const float* kb     = (const float*)d_in[10];
    const float* vw     = (const float*)d_in[11];
    const float* vb     = (const float*)d_in[12];
    const float* ow     = (const float*)d_in[13];
    const float* ob     = (const float*)d_in[14];
    const float* ln2_g  = (const float*)d_in[15];
    const float* ln2_b  = (const float*)d_in[16];
    const float* fcw    = (const float*)d_in[17];
    const float* fcb    = (const float*)d_in[18];
    const float* pw     = (const float*)d_in[19];
    const float* pb     = (const float*)d_in[20];
    const float* lnf_g  = (const float*)d_in[21];
    const float* lnf_b  = (const float*)d_in[22];
    const float* head_w = (const float*)d_in[23];
    const float* head_b = (const float*)d_in[24];

    __half *Wh, *Wl, *Th, *Tl, *Yh, *Yl, *Ohb, *Olb, *Mh, *Ml;
    float *E, *H, *Y, *QKV, *S, *qkvb;
    cudaGetSymbolAddress((void**)&Wh,  g_Wh);
    cudaGetSymbolAddress((void**)&Wl,  g_Wl);
    cudaGetSymbolAddress((void**)&Th,  g_Th);
    cudaGetSymbolAddress((void**)&Tl,  g_Tl);
    cudaGetSymbolAddress((void**)&Yh,  g_Yh);
    cudaGetSymbolAddress((void**)&Yl,  g_Yl);
    cudaGetSymbolAddress((void**)&Ohb, g_Oh);
    cudaGetSymbolAddress((void**)&Olb, g_Ol);
    cudaGetSymbolAddress((void**)&Mh,  g_Mh);
    cudaGetSymbolAddress((void**)&Ml,  g_Ml);
    cudaGetSymbolAddress((void**)&E,   g_E);
    cudaGetSymbolAddress((void**)&H,   g_H);
    cudaGetSymbolAddress((void**)&Y,   g_Y);
    cudaGetSymbolAddress((void**)&QKV, g_QKV);
    cudaGetSymbolAddress((void**)&S,   g_S);
    cudaGetSymbolAddress((void**)&qkvb,g_qkvb);

    dim3 tb(32, 8);
    // ---- weight prep ----
    transp_split_kernel<<<dim3(24, 24), tb>>>(proj_w, Wh + W_PATCH_OFF, Wl + W_PATCH_OFF, 768, 768);
    for (int l = 0; l < LYRS; l++) {
        size_t base = W_PATCH_SZ + (size_t)l * W_LAYER_SZ;
        const size_t w768 = (size_t)l * 768 * 768;
        transp_split_kernel<<<dim3(24, 24), tb>>>(qw + w768, Wh + base,              Wl + base,              768, 768);
        transp_split_kernel<<<dim3(24, 24), tb>>>(kw + w768, Wh + base + 768 * 768,  Wl + base + 768 * 768,  768, 768);
        transp_split_kernel<<<dim3(24, 24), tb>>>(vw + w768, Wh + base + 1536 * 768, Wl + base + 1536 * 768, 768, 768);
        transp_split_kernel<<<dim3(24, 24), tb>>>(ow + w768, Wh + base + W_O_OFF,    Wl + base + W_O_OFF,    768, 768);
        transp_split_kernel<<<dim3(96, 24), tb>>>(fcw + (size_t)l * 768 * 3072,
                                                  Wh + base + W_FC_OFF, Wl + base + W_FC_OFF, 768, 3072);
        transp_split_kernel<<<dim3(24, 96), tb>>>(pw + (size_t)l * 3072 * 768,
                                                  Wh + base + W_PW_OFF, Wl + base + W_PW_OFF, 3072, 768);
    }
    biaspack_kernel<<<(LYRS * QSTR + 255) / 256, 256>>>(qb, kb, vb, qkvb);

    // ---- patch embed ----
    patch_gather_kernel<<<(PROWS * DMODEL + 255) / 256, 256>>>(x, Th, Tl);
    gemm_h_kernel<<<dim3(6, 36), 256>>>(
        Th, Tl, Wh + W_PATCH_OFF, Wl + W_PATCH_OFF, proj_b, E,
        (__half*)0, (__half*)0, PROWS, 768, 768, 0);
    assemble_kernel<<<(TOKS * DMODEL + 255) / 256, 256>>>(E, cls_e, pos_e, H);

    for (int l = 0; l < LYRS; l++) {
        size_t base = W_PATCH_SZ + (size_t)l * W_LAYER_SZ;
        const size_t bo  = (size_t)l * DMODEL;
        const size_t fbo = (size_t)l * MLPD;

        ln_split_kernel<<<TOKS, 256>>>(H, ln1_g + bo, ln1_b + bo, Yh, Yl);
        gemm_h_kernel<<<dim3(18, 37), 256>>>(
            Yh, Yl, Wh + base + W_QKV_OFF, Wl + base + W_QKV_OFF, qkvb + (size_t)l * QSTR,
            QKV, (__half*)0, (__half*)0, TOKS, QSTR, 768, 0);

        attn_scores_kernel<<<dim3(10, 10, BATCH * NHEAD), 256>>>(QKV, S);
        softmax_kernel<<<BATCH * NHEAD * NTOK, 128>>>(S);
        attn_out_kernel<<<dim3(1, 10, BATCH * NHEAD), 256>>>(S, QKV, Ohb, Olb);

        gemm_h_kernel<<<dim3(6, 37), 256>>>(
            Ohb, Olb, Wh + base + W_O_OFF, Wl + base + W_O_OFF, ob + bo,
            H, (__half*)0, (__half*)0, TOKS, 768, 768, 1);

        ln_split_kernel<<<TOKS, 256>>>(H, ln2_g + bo, ln2_b + bo, Yh, Yl);
        gemm_h_kernel<<<dim3(24, 37), 256>>>(
            Yh, Yl, Wh + base + W_FC_OFF, Wl + base + W_FC_OFF, fcb + fbo,
            (float*)0, Mh, Ml, TOKS, MLPD, 768, 2);
        gemm_h_kernel<<<dim3(6, 37), 256>>>(
            Mh, Ml, Wh + base + W_PW_OFF, Wl + base + W_PW_OFF, pb + bo,
            H, (__half*)0, (__half*)0, TOKS, 768, 3072, 1);
    }

    layernorm_kernel<<<TOKS, 256>>>(H, lnf_g, lnf_b, Y);
    head_kernel<<<(BATCH * NCLS + 255) / 256, 256>>>(Y, head_w, head_b, (float*)d_out);
}

// round 16
// speedup vs baseline: 2.5149x; 1.3633x over previous
#include <cuda_runtime.h>
#include <cuda_fp16.h>
#include <math.h>
#include <stdint.h>

// ---------------- Config ----------------
#define BATCH 8
#define CCH   3
#define IMG   384
#define NP    576
#define NTOK  577
#define DMODEL 768
#define NHEAD 12
#define HD    64
#define LYRS  12
#define MLPD  3072
#define NCLS  1000

#define TOKS   (BATCH*NTOK)      // 4616
#define TOKS_P 4736
#define PROWS  (BATCH*NP)        // 4608
#define SP     608               // padded S row stride (multiple of 32)
#define QSTR   2304              // fused QKV row stride

// Weight split buffer offsets (elements). Layout per matrix: [N][K] half.
#define W_PATCH_OFF 0
#define W_PATCH_SZ  (768*768)
#define W_LAYER_SZ  (2304*768 + 768*768 + 3072*768 + 768*3072)
#define W_QKV_OFF   0
#define W_O_OFF     (2304*768)
#define W_FC_OFF    (W_O_OFF + 768*768)
#define W_PW_OFF    (W_FC_OFF + 3072*768)
#define W_TOTAL     (W_PATCH_SZ + 12*W_LAYER_SZ)

// ---------------- Scratch ----------------
__device__ __align__(256) __half g_Wh[W_TOTAL];
__device__ __align__(256) __half g_Wl[W_TOTAL];
__device__ __align__(256) __half g_Th[PROWS*DMODEL];
__device__ __align__(256) __half g_Tl[PROWS*DMODEL];
__device__ __align__(256) __half g_Yh[TOKS_P*DMODEL];
__device__ __align__(256) __half g_Yl[TOKS_P*DMODEL];
__device__ __align__(256) __half g_Oh[TOKS_P*DMODEL];
__device__ __align__(256) __half g_Ol[TOKS_P*DMODEL];
__device__ __align__(256) __half g_Mh[(size_t)TOKS_P*MLPD];
__device__ __align__(256) __half g_Ml[(size_t)TOKS_P*MLPD];
__device__ __align__(256) __half g_QKVh[(size_t)TOKS*QSTR];
__device__ __align__(256) __half g_QKVl[(size_t)TOKS*QSTR];
__device__ __align__(256) __half g_Ph[(size_t)BATCH*NHEAD*NTOK*SP];
__device__ __align__(256) __half g_Pl[(size_t)BATCH*NHEAD*NTOK*SP];
__device__ float g_E[PROWS*DMODEL];
__device__ float g_H[TOKS*DMODEL];
__device__ float g_Y[TOKS*DMODEL];
__device__ float g_S[(size_t)BATCH*NHEAD*NTOK*SP];
__device__ float g_qkvb[LYRS*QSTR];

// ---------------- helpers ----------------
__device__ __forceinline__ uint32_t smem_u32(const void* p) {
    uint32_t a;
    asm("{ .reg .u64 t; cvta.to.shared.u64 t, %1; cvt.u32.u64 %0, t; }" : "=r"(a) : "l"(p));
    return a;
}
__device__ __forceinline__ float gelu_exact(float x) {
    return 0.5f * x * (1.0f + erff(x * 0.70710678118654752f));
}
__device__ __forceinline__ void hsplit(float x, __half& h, __half& l) {
    h = __float2half_rn(x);
    l = __float2half_rn(x - __half2float(h));
}

#define LDSM_X4(r0, r1, r2, r3, addr)                                          \
    asm volatile("ldmatrix.sync.aligned.m8n8.x4.shared.b16 {%0,%1,%2,%3}, [%4];" \
                 : "=r"(r0), "=r"(r1), "=r"(r2), "=r"(r3) : "r"(addr))
#define LDSM_X4_T(r0, r1, r2, r3, addr)                                        \
    asm volatile("ldmatrix.sync.aligned.m8n8.x4.trans.shared.b16 {%0,%1,%2,%3}, [%4];" \
                 : "=r"(r0), "=r"(r1), "=r"(r2), "=r"(r3) : "r"(addr))

#define MMA16816(d, a0, a1, a2, a3, b0, b1)                                    \
    asm volatile("mma.sync.aligned.m16n8k16.row.col.f32.f16.f16.f32 "          \
                 "{%0,%1,%2,%3},{%4,%5,%6,%7},{%8,%9},{%0,%1,%2,%3};"          \
                 : "+f"((d)[0]), "+f"((d)[1]), "+f"((d)[2]), "+f"((d)[3])      \
                 : "r"(a0), "r"(a1), "r"(a2), "r"(a3), "r"(b0), "r"(b1))

// ---------------- fp16-split HMMA GEMM ----------------
// C = A @ W^T + bias. 3 passes (hh + hl + lh), fp32 accum.
// mode 0: Cf=v+b; 1: Cf=v+b+Cf(res); 2: gelu(v+b) split->Ch/Cl; 3: (v+b) split->Ch/Cl.
#define ASTR 40

__global__ __launch_bounds__(256, 1) void gemm_h_kernel(
    const __half* __restrict__ Ah, const __half* __restrict__ Al,
    const __half* __restrict__ Wh, const __half* __restrict__ Wl,
    const float* __restrict__ bias, float* Cf,
    __half* __restrict__ Ch, __half* __restrict__ Cl,
    int M, int N, int K, int mode)
{
    __shared__ __half sAh[128 * ASTR];
    __shared__ __half sAl[128 * ASTR];
    __shared__ __half sBh[128 * ASTR];
    __shared__ __half sBl[128 * ASTR];

    const int tid  = threadIdx.x;
    const int lane = tid & 31;
    const int w    = tid >> 5;
    const int wm   = w & 3;
    const int wn   = w >> 2;
    const int bm = blockIdx.y * 128;
    const int bn = blockIdx.x * 128;

    const uint32_t uAh = smem_u32(sAh), uAl = smem_u32(sAl);
    const uint32_t uBh = smem_u32(sBh), uBl = smem_u32(sBl);

    const int lr0 = tid >> 2,          lk0 = (tid & 3) * 8;
    const int lr1 = (tid + 256) >> 2,  lk1 = lk0;

    const int arow = wm * 32 + (lane & 15);
    const int acol = (lane >> 4) * 8;
    const int brow_base = wn * 64 + (lane & 7) + ((lane >> 4) << 3);
    const int bcol = (lane & 8);

    float acc[2][8][4];
#pragma unroll
    for (int i = 0; i < 2; i++)
#pragma unroll
        for (int j = 0; j < 8; j++)
#pragma unroll
            for (int q = 0; q < 4; q++) acc[i][j][q] = 0.f;

    const int nt = K >> 5;
    float4 rAh0, rAh1, rAl0, rAl1, rBh0, rBh1, rBl0, rBl1;

    rAh0 = *(const float4*)(Ah + (size_t)(bm + lr0) * K + lk0);
    rAh1 = *(const float4*)(Ah + (size_t)(bm + lr1) * K + lk1);
    rAl0 = *(const float4*)(Al + (size_t)(bm + lr0) * K + lk0);
    rAl1 = *(const float4*)(Al + (size_t)(bm + lr1) * K + lk1);
    rBh0 = *(const float4*)(Wh + (size_t)(bn + lr0) * K + lk0);
    rBh1 = *(const float4*)(Wh + (size_t)(bn + lr1) * K + lk1);
    rBl0 = *(const float4*)(Wl + (size_t)(bn + lr0) * K + lk0);
    rBl1 = *(const float4*)(Wl + (size_t)(bn + lr1) * K + lk1);

    *(float4*)&sAh[lr0 * ASTR + lk0] = rAh0; *(float4*)&sAh[lr1 * ASTR + lk1] = rAh1;
    *(float4*)&sAl[lr0 * ASTR + lk0] = rAl0; *(float4*)&sAl[lr1 * ASTR + lk1] = rAl1;
    *(float4*)&sBh[lr0 * ASTR + lk0] = rBh0; *(float4*)&sBh[lr1 * ASTR + lk1] = rBh1;
    *(float4*)&sBl[lr0 * ASTR + lk0] = rBl0; *(float4*)&sBl[lr1 * ASTR + lk1] = rBl1;
    __syncthreads();

    for (int t = 0; t < nt; t++) {
        const bool more = (t + 1 < nt);
        if (more) {
            const int k0 = (t + 1) << 5;
            rAh0 = *(const float4*)(Ah + (size_t)(bm + lr0) * K + k0 + lk0);
            rAh1 = *(const float4*)(Ah + (size_t)(bm + lr1) * K + k0 + lk1);
            rAl0 = *(const float4*)(Al + (size_t)(bm + lr0) * K + k0 + lk0);
            rAl1 = *(const float4*)(Al + (size_t)(bm + lr1) * K + k0 + lk1);
            rBh0 = *(const float4*)(Wh + (size_t)(bn + lr0) * K + k0 + lk0);
            rBh1 = *(const float4*)(Wh + (size_t)(bn + lr1) * K + k0 + lk1);
            rBl0 = *(const float4*)(Wl + (size_t)(bn + lr0) * K + k0 + lk0);
            rBl1 = *(const float4*)(Wl + (size_t)(bn + lr1) * K + k0 + lk1);
        }

#pragma unroll
        for (int k16 = 0; k16 < 2; k16++) {
            const int kc = k16 * 16;
            uint32_t ah[2][4], al2[2][4];
#pragma unroll
            for (int am = 0; am < 2; am++) {
                uint32_t off = ((arow + am * 16) * ASTR + kc + acol) * 2;
                LDSM_X4(ah[am][0], ah[am][1], ah[am][2], ah[am][3], uAh + off);
                LDSM_X4(al2[am][0], al2[am][1], al2[am][2], al2[am][3], uAl + off);
            }
            uint32_t bh[4][4], bl[4][4];
#pragma unroll
            for (int j = 0; j < 4; j++) {
                uint32_t off = ((brow_base + j * 16) * ASTR + kc + bcol) * 2;
                LDSM_X4(bh[j][0], bh[j][1], bh[j][2], bh[j][3], uBh + off);
                LDSM_X4(bl[j][0], bl[j][1], bl[j][2], bl[j][3], uBl + off);
            }
#pragma unroll
            for (int am = 0; am < 2; am++) {
#pragma unroll
                for (int jj = 0; jj < 8; jj++) {
                    const int jx = jj >> 1, sel = (jj & 1) * 2;
                    MMA16816(acc[am][jj], ah[am][0], ah[am][1], ah[am][2], ah[am][3],
                             bh[jx][sel], bh[jx][sel + 1]);
                    MMA16816(acc[am][jj], ah[am][0], ah[am][1], ah[am][2], ah[am][3],
                             bl[jx][sel], bl[jx][sel + 1]);
                    MMA16816(acc[am][jj], al2[am][0], al2[am][1], al2[am][2], al2[am][3],
                             bh[jx][sel], bh[jx][sel + 1]);
                }
            }
        }

        if (more) {
            __syncthreads();
            *(float4*)&sAh[lr0 * ASTR + lk0] = rAh0; *(float4*)&sAh[lr1 * ASTR + lk1] = rAh1;
            *(float4*)&sAl[lr0 * ASTR + lk0] = rAl0; *(float4*)&sAl[lr1 * ASTR + lk1] = rAl1;
            *(float4*)&sBh[lr0 * ASTR + lk0] = rBh0; *(float4*)&sBh[lr1 * ASTR + lk1] = rBh1;
            *(float4*)&sBl[lr0 * ASTR + lk0] = rBl0; *(float4*)&sBl[lr1 * ASTR + lk1] = rBl1;
            __syncthreads();
        }
    }

    const int gRow0 = bm + wm * 32 + (lane >> 2);
    const int gCol0 = bn + wn * 64 + (lane & 3) * 2;
#pragma unroll
    for (int am = 0; am < 2; am++) {
#pragma unroll
        for (int jj = 0; jj < 8; jj++) {
            const int gc = gCol0 + jj * 8;
            const float2 b2 = *(const float2*)(bias + gc);
#pragma unroll
            for (int hrow = 0; hrow < 2; hrow++) {
                const int gr = gRow0 + am * 16 + hrow * 8;
                if (gr >= M) continue;
                float x0 = acc[am][jj][hrow * 2 + 0] + b2.x;
                float x1 = acc[am][jj][hrow * 2 + 1] + b2.y;
                if (mode <= 1) {
                    if (mode == 1) {
                        float2 rv = *(const float2*)(Cf + (size_t)gr * N + gc);
                        x0 += rv.x; x1 += rv.y;
                    }
                    *(float2*)(Cf + (size_t)gr * N + gc) = make_float2(x0, x1);
                } else {
                    if (mode == 2) { x0 = gelu_exact(x0); x1 = gelu_exact(x1); }
                    __half h0, l0, h1, l1;
                    hsplit(x0, h0, l0); hsplit(x1, h1, l1);
                    *(__half2*)(Ch + (size_t)gr * N + gc) = __halves2half2(h0, h1);
                    *(__half2*)(Cl + (size_t)gr * N + gc) = __halves2half2(l0, l1);
                }
            }
        }
    }
}

// ---------------- Attention scores: S = scale * Q @ K^T (HMMA, 3-pass split) ----------------
#define SSTR 72   // smem row stride (halves): conflict-free ldmatrix
__global__ __launch_bounds__(256, 1) void attn_scores_h(
    const __half* __restrict__ QKVh, const __half* __restrict__ QKVl,
    float* __restrict__ S)
{
    extern __shared__ __half sm[];
    __half* sQh = sm;
    __half* sQl = sm + 128 * SSTR;
    __half* sKh = sm + 2 * 128 * SSTR;
    __half* sKl = sm + 3 * 128 * SSTR;

    const int bh = blockIdx.z;
    const int b = bh / NHEAD, h = bh - b * NHEAD;
    const int m0 = blockIdx.y * 128, n0 = blockIdx.x * 128;
    const int tid = threadIdx.x, lane = tid & 31, w = tid >> 5;
    const int wm = w & 3, wn = w >> 2;

    const size_t qoff = (size_t)b * NTOK * QSTR + h * HD;
    const size_t koff = qoff + 768;

#pragma unroll
    for (int i = 0; i < 4; i++) {
        int idx = tid + i * 256;            // 0..1023
        int r = idx >> 3, c8 = (idx & 7) * 8;
        float4 z4 = make_float4(0.f, 0.f, 0.f, 0.f);
        float4 qh = z4, ql = z4, kh = z4, kl = z4;
        if (m0 + r < NTOK) {
            qh = *(const float4*)(QKVh + qoff + (size_t)(m0 + r) * QSTR + c8);
            ql = *(const float4*)(QKVl + qoff + (size_t)(m0 + r) * QSTR + c8);
        }
        if (n0 + r < NTOK) {
            kh = *(const float4*)(QKVh + koff + (size_t)(n0 + r) * QSTR + c8);
            kl = *(const float4*)(QKVl + koff + (size_t)(n0 + r) * QSTR + c8);
        }
        *(float4*)&sQh[r * SSTR + c8] = qh;
        *(float4*)&sQl[r * SSTR + c8] = ql;
        *(float4*)&sKh[r * SSTR + c8] = kh;
        *(float4*)&sKl[r * SSTR + c8] = kl;
    }
    __syncthreads();

    const uint32_t uQh = smem_u32(sQh), uQl = smem_u32(sQl);
    const uint32_t uKh = smem_u32(sKh), uKl = smem_u32(sKl);
    const int arow = wm * 32 + (lane & 15);
    const int acol = (lane >> 4) * 8;
    const int brow_base = wn * 64 + (lane & 7) + ((lane >> 4) << 3);
    const int bcol = (lane & 8);

    float acc[2][8][4];
#pragma unroll
    for (int i = 0; i < 2; i++)
#pragma unroll
        for (int j = 0; j < 8; j++)
#pragma unroll
            for (int q = 0; q < 4; q++) acc[i][j][q] = 0.f;

#pragma unroll
    for (int k16 = 0; k16 < 4; k16++) {
        const int kc = k16 * 16;
        uint32_t ah[2][4], al2[2][4];
#pragma unroll
        for (int am = 0; am < 2; am++) {
            uint32_t off = ((arow + am * 16) * SSTR + kc + acol) * 2;
            LDSM_X4(ah[am][0], ah[am][1], ah[am][2], ah[am][3], uQh + off);
            LDSM_X4(al2[am][0], al2[am][1], al2[am][2], al2[am][3], uQl + off);
        }
        uint32_t bhf[4][4], blf[4][4];
#pragma unroll
        for (int j = 0; j < 4; j++) {
            uint32_t off = ((brow_base + j * 16) * SSTR + kc + bcol) * 2;
            LDSM_X4(bhf[j][0], bhf[j][1], bhf[j][2], bhf[j][3], uKh + off);
            LDSM_X4(blf[j][0], blf[j][1], blf[j][2], blf[j][3], uKl + off);
        }
#pragma unroll
        for (int am = 0; am < 2; am++) {
#pragma unroll
            for (int jj = 0; jj < 8; jj++) {
                const int jx = jj >> 1, sel = (jj & 1) * 2;
                MMA16816(acc[am][jj], ah[am][0], ah[am][1], ah[am][2], ah[am][3],
                         bhf[jx][sel], bhf[jx][sel + 1]);
                MMA16816(acc[am][jj], ah[am][0], ah[am][1], ah[am][2], ah[am][3],
                         blf[jx][sel], blf[jx][sel + 1]);
                MMA16816(acc[am][jj], al2[am][0], al2[am][1], al2[am][2], al2[am][3],
                         bhf[jx][sel], bhf[jx][sel + 1]);
            }
        }
    }

    float* Sb = S + (size_t)bh * NTOK * SP;
    const int gr0 = m0 + wm * 32 + (lane >> 2);
    const int gc0 = n0 + wn * 64 + (lane & 3) * 2;
#pragma unroll
    for (int am = 0; am < 2; am++) {
#pragma unroll
        for (int hrow = 0; hrow < 2; hrow++) {
            const int gr = gr0 + am * 16 + hrow * 8;
            if (gr >= NTOK) continue;
#pragma unroll
            for (int jj = 0; jj < 8; jj++) {
                const int gc = gc0 + jj * 8;
                if (gc >= NTOK) continue;   // pad cols never read
                *(float2*)(Sb + (size_t)gr * SP + gc) =
                    make_float2(acc[am][jj][hrow * 2] * 0.125f,
                                acc[am][jj][hrow * 2 + 1] * 0.125f);
            }
        }
    }
}

// ---------------- Softmax: fp32 S row -> split halves Ph/Pl (pads zeroed) ----------------
__global__ void softmax_split_kernel(const float* __restrict__ S,
                                     __half* __restrict__ Ph, __half* __restrict__ Pl)
{
    int r  = blockIdx.x;
    int bh = r / NTOK, m = r - bh * NTOK;
    const size_t ro = (size_t)bh * NTOK * SP + (size_t)m * SP;
    const float* row = S + ro;
    int tid = threadIdx.x;   // 128

    float lmax = -3.4e38f;
    for (int c = tid; c < NTOK; c += 128) lmax = fmaxf(lmax, row[c]);
#pragma unroll
    for (int o = 16; o; o >>= 1) lmax = fmaxf(lmax, __shfl_xor_sync(0xffffffffu, lmax, o));
    __shared__ float sred[4];
    if ((tid & 31) == 0) sred[tid >> 5] = lmax;
    __syncthreads();
    float bmax = fmaxf(fmaxf(sred[0], sred[1]), fmaxf(sred[2], sred[3]));
    __syncthreads();

    float ev[5];
    float lsum = 0.f;
    int cnt = 0;
    for (int c = tid; c < NTOK; c += 128) {
        float e = expf(row[c] - bmax);
        ev[cnt++] = e;
        lsum += e;
    }
#pragma unroll
    for (int o = 16; o; o >>= 1) lsum += __shfl_xor_sync(0xffffffffu, lsum, o);
    if ((tid & 31) == 0) sred[tid >> 5] = lsum;
    __syncthreads();
    float inv = 1.0f / (sred[0] + sred[1] + sred[2] + sred[3]);

    cnt = 0;
    for (int c = tid; c < NTOK; c += 128) {
        __half hh, ll;
        hsplit(ev[cnt++] * inv, hh, ll);
        Ph[ro + c] = hh;
        Pl[ro + c] = ll;
    }
    if (tid < SP - NTOK) {
        Ph[ro + NTOK + tid] = __float2half(0.f);
        Pl[ro + NTOK + tid] = __float2half(0.f);
    }
}

// ---------------- PV: O = P @ V (HMMA, 3-pass split, V via ldmatrix.trans) ----------------
#define VSTR 72
__global__ __launch_bounds__(256, 1) void attn_pv_h(
    const __half* __restrict__ Ph, const __half* __restrict__ Pl,
    const __half* __restrict__ QKVh, const __half* __restrict__ QKVl,
    __half* __restrict__ Oh, __half* __restrict__ Ol)
{
    __shared__ __half sPh[128 * ASTR];
    __shared__ __half sPl[128 * ASTR];
    __shared__ __half sVh[32 * VSTR];
    __shared__ __half sVl[32 * VSTR];

    const int bh = blockIdx.y;
    const int b = bh / NHEAD, h = bh - b * NHEAD;
    const int m0 = blockIdx.x * 128;
    const int tid = threadIdx.x, lane = tid & 31, w = tid >> 5;
    const int wm = w & 3, wn = w >> 2;

    const size_t pbase = (size_t)bh * NTOK * SP;
    const size_t vbase = (size_t)b * NTOK * QSTR + 1536 + h * HD;

    const uint32_t uPh = smem_u32(sPh), uPl = smem_u32(sPl);
    const uint32_t uVh = smem_u32(sVh), uVl = smem_u32(sVl);

    float acc[2][4][4];
#pragma unroll
    for (int i = 0; i < 2; i++)
#pragma unroll
        for (int j = 0; j < 4; j++)
#pragma unroll
            for (int q = 0; q < 4; q++) acc[i][j][q] = 0.f;

    const int arow = wm * 32 + (lane & 15);
    const int acol = (lane >> 4) * 8;
    const int bk   = (lane & 7) + ((lane >> 3) & 1) * 8;   // k within 16
    const int bn_  = wn * 32 + (lane >> 4) * 8;            // n base (j adds 16)

    for (int k0 = 0; k0 < SP; k0 += 32) {
#pragma unroll
        for (int i = 0; i < 2; i++) {
            int idx = tid + i * 256;          // 0..511
            int r = idx >> 2, c8 = (idx & 3) * 8;
            float4 p4 = make_float4(0.f, 0.f, 0.f, 0.f), q4 = p4;
            if (m0 + r < NTOK) {
                p4 = *(const float4*)(Ph + pbase + (size_t)(m0 + r) * SP + k0 + c8);
                q4 = *(const float4*)(Pl + pbase + (size_t)(m0 + r) * SP + k0 + c8);
            }
            *(float4*)&sPh[r * ASTR + c8] = p4;
            *(float4*)&sPl[r * ASTR + c8] = q4;
        }
        {
            int r = tid >> 3, c8 = (tid & 7) * 8;   // 32 rows x 64 cols
            float4 v4 = make_float4(0.f, 0.f, 0.f, 0.f), u4 = v4;
            if (k0 + r < NTOK) {
                v4 = *(const float4*)(QKVh + vbase + (size_t)(k0 + r) * QSTR + c8);
                u4 = *(const float4*)(QKVl + vbase + (size_t)(k0 + r) * QSTR + c8);
            }
            *(float4*)&sVh[r * VSTR + c8] = v4;
            *(float4*)&sVl[r * VSTR + c8] = u4;
        }
        __syncthreads();

#pragma unroll
        for (int k16 = 0; k16 < 2; k16++) {
            const int kc = k16 * 16;
            uint32_t ah[2][4], al2[2][4];
#pragma unroll
            for (int am = 0; am < 2; am++) {
                uint32_t off = ((arow + am * 16) * ASTR + kc + acol) * 2;
                LDSM_X4(ah[am][0], ah[am][1], ah[am][2], ah[am][3], uPh + off);
                LDSM_X4(al2[am][0], al2[am][1], al2[am][2], al2[am][3], uPl + off);
            }
            uint32_t bhf[2][4], blf[2][4];
#pragma unroll
            for (int j = 0; j < 2; j++) {
                uint32_t off = ((kc + bk) * VSTR + bn_ + j * 16) * 2;
                LDSM_X4_T(bhf[j][0], bhf[j][1], bhf[j][2], bhf[j][3], uVh + off);
                LDSM_X4_T(blf[j][0], blf[j][1], blf[j][2], blf[j][3], uVl + off);
            }
#pragma unroll
            for (int am = 0; am < 2; am++) {
#pragma unroll
                for (int jj = 0; jj < 4; jj++) {
                    const int jx = jj >> 1, sel = (jj & 1) * 2;
                    MMA16816(acc[am][jj], ah[am][0], ah[am][1], ah[am][2], ah[am][3],
                             bhf[jx][sel], bhf[jx][sel + 1]);
                    MMA16816(acc[am][jj], ah[am][0], ah[am][1], ah[am][2], ah[am][3],
                             blf[jx][sel], blf[jx][sel + 1]);
                    MMA16816(acc[am][jj], al2[am][0], al2[am][1], al2[am][2], al2[am][3],
                             bhf[jx][sel], bhf[jx][sel + 1]);
                }
            }
        }
        __syncthreads();
    }

    const int gr0 = m0 + wm * 32 + (lane >> 2);
    const int gc0 = wn * 32 + (lane & 3) * 2;
#pragma unroll
    for (int am = 0; am < 2; am++) {
#pragma unroll
        for (int hrow = 0; hrow < 2; hrow++) {
            const int gr = gr0 + am * 16 + hrow * 8;
            if (gr >= NTOK) continue;
            const size_t rbase = ((size_t)(b * NTOK + gr)) * DMODEL + h * HD;
#pragma unroll
            for (int jj = 0; jj < 4; jj++) {
                const int gc = gc0 + jj * 8;
                __half h0, l0, h1, l1;
                hsplit(acc[am][jj][hrow * 2 + 0], h0, l0);
                hsplit(acc[am][jj][hrow * 2 + 1], h1, l1);
                *(__half2*)(Oh + rbase + gc) = __halves2half2(h0, h1);
                *(__half2*)(Ol + rbase + gc) = __halves2half2(l0, l1);
            }
        }
    }
}

// ---------------- Weight transpose + split (batched over layers via grid.z) ----------------
__global__ void transp_split_kernel(const float* __restrict__ src, size_t srcStride,
                                    __half* __restrict__ dh, __half* __restrict__ dl,
                                    size_t dstStride, int K, int N)
{
    __shared__ float t[32][33];
    const float* s = src + (size_t)blockIdx.z * srcStride;
    __half* dhh = dh + (size_t)blockIdx.z * dstStride;
    __half* dll = dl + (size_t)blockIdx.z * dstStride;
    int k0 = blockIdx.y * 32, n0 = blockIdx.x * 32;
    int tx = threadIdx.x, ty = threadIdx.y;   // (32, 8)
#pragma unroll
    for (int j = 0; j < 4; j++)
        t[ty + j * 8][tx] = s[(size_t)(k0 + ty + j * 8) * N + n0 + tx];
    __syncthreads();
#pragma unroll
    for (int j = 0; j < 4; j++) {
        int n = n0 + ty + j * 8;
        float v = t[tx][ty + j * 8];
        __half h, l; hsplit(v, h, l);
        dhh[(size_t)n * K + k0 + tx] = h;
        dll[(size_t)n * K + k0 + tx] = l;
    }
}

// ---------------- QKV bias pack ----------------
__global__ void biaspack_kernel(const float* qb, const float* kb, const float* vb, float* out)
{
    int idx = blockIdx.x * blockDim.x + threadIdx.x;
    if (idx >= LYRS * QSTR) return;
    int l = idx / QSTR, c = idx - l * QSTR;
    float v = (c < 768) ? qb[l * 768 + c] : (c < 1536) ? kb[l * 768 + c - 768] : vb[l * 768 + c - 1536];
    out[idx] = v;
}

// ---------------- Patch gather (faithful buggy flattening) + split ----------------
__global__ void patch_gather_kernel(const float* __restrict__ x,
                                    __half* __restrict__ Th, __half* __restrict__ Tl)
{
    int idx = blockIdx.x * blockDim.x + threadIdx.x;
    if (idx >= PROWS * DMODEL) return;
    int p1  = idx / 221184;
    int rem = idx % 221184;
    int m   = rem >> 4;
    int p2  = rem & 15;
    int b   = m / 1728;
    int mm  = m - b * 1728;
    int c   = mm / 576;
    int mg  = mm - c * 576;
    int gh  = mg / 24;
    int gw  = mg - gh * 24;
    float v = x[(((size_t)(b * CCH + c) * IMG) + gh * 16 + p1) * IMG + gw * 16 + p2];
    __half h, l; hsplit(v, h, l);
    Th[idx] = h; Tl[idx] = l;
}

// ---------------- Assemble tokens ----------------
__global__ void assemble_kernel(const float* __restrict__ E, const float* __restrict__ cls,
                                const float* __restrict__ pos, float* __restrict__ H)
{
    int idx = blockIdx.x * blockDim.x + threadIdx.x;
    if (idx >= TOKS * DMODEL) return;
    int tok = idx / DMODEL;
    int k   = idx - tok * DMODEL;
    int b   = tok / NTOK;
    int n   = tok - b * NTOK;
    float v = (n == 0) ? cls[k] : E[((size_t)(b * NP + n - 1)) * DMODEL + k];
    H[idx] = v + pos[(size_t)n * DMODEL + k];
}

// ---------------- LayerNorm: split output ----------------
__global__ void ln_split_kernel(const float* __restrict__ X, const float* __restrict__ g,
                                const float* __restrict__ bta,
                                __half* __restrict__ Yh, __half* __restrict__ Yl)
{
    int r = blockIdx.x;
    const float* xr = X + (size_t)r * DMODEL;
    int tid = threadIdx.x;
    float v0 = xr[tid], v1 = xr[tid + 256], v2 = xr[tid + 512];
    float s  = v0 + v1 + v2;
    float s2 = v0 * v0 + v1 * v1 + v2 * v2;
#pragma unroll
    for (int o = 16; o; o >>= 1) {
        s  += __shfl_xor_sync(0xffffffffu, s,  o);
        s2 += __shfl_xor_sync(0xffffffffu, s2, o);
    }
    __shared__ float r1[8], r2[8];
    if ((tid & 31) == 0) { r1[tid >> 5] = s; r2[tid >> 5] = s2; }
    __syncthreads();
    float S = 0.f, S2 = 0.f;
#pragma unroll
    for (int ww = 0; ww < 8; ww++) { S += r1[ww]; S2 += r2[ww]; }
    float mean = S * (1.0f / 768.0f);
    float var  = S2 * (1.0f / 768.0f) - mean * mean;
    float inv  = rsqrtf(var + 1e-5f);
#pragma unroll
    for (int j = 0; j < 3; j++) {
        int c = tid + j * 256;
        float y = (xr[c] - mean) * inv * g[c] + bta[c];
        __half h, l; hsplit(y, h, l);
        Yh[(size_t)r * DMODEL + c] = h;
        Yl[(size_t)r * DMODEL + c] = l;
    }
}

// ---------------- LayerNorm fp32 out (final) ----------------
__global__ void layernorm_kernel(const float* __restrict__ X, const float* __restrict__ g,
                                 const float* __restrict__ bta, float* __restrict__ Y)
{
    int r = blockIdx.x;
    const float* xr = X + (size_t)r * DMODEL;
    float* yr = Y + (size_t)r * DMODEL;
    int tid = threadIdx.x;
    float v0 = xr[tid], v1 = xr[tid + 256], v2 = xr[tid + 512];
    float s  = v0 + v1 + v2;
    float s2 = v0 * v0 + v1 * v1 + v2 * v2;
#pragma unroll
    for (int o = 16; o; o >>= 1) {
        s  += __shfl_xor_sync(0xffffffffu, s,  o);
        s2 += __shfl_xor_sync(0xffffffffu, s2, o);
    }
    __shared__ float r1[8], r2[8];
    if ((tid & 31) == 0) { r1[tid >> 5] = s; r2[tid >> 5] = s2; }
    __syncthreads();
    float S = 0.f, S2 = 0.f;
#pragma unroll
    for (int ww = 0; ww < 8; ww++) { S += r1[ww]; S2 += r2[ww]; }
    float mean = S * (1.0f / 768.0f);
    float var  = S2 * (1.0f / 768.0f) - mean * mean;
    float inv  = rsqrtf(var + 1e-5f);
    yr[tid]       = (v0 - mean) * inv * g[tid]       + bta[tid];
    yr[tid + 256] = (v1 - mean) * inv * g[tid + 256] + bta[tid + 256];
    yr[tid + 512] = (v2 - mean) * inv * g[tid + 512] + bta[tid + 512];
}

// ---------------- Classifier head ----------------
__global__ void head_kernel(const float* __restrict__ Hln, const float* __restrict__ W,
                            const float* __restrict__ bias, float* __restrict__ out)
{
    int idx = blockIdx.x * blockDim.x + threadIdx.x;
    if (idx >= BATCH * NCLS) return;
    int b = idx / NCLS, c = idx - b * NCLS;
    const float* hr = Hln + (size_t)b * NTOK * DMODEL;
    float s = bias[c];
#pragma unroll 4
    for (int d = 0; d < DMODEL; d++) s += hr[d] * W[(size_t)d * NCLS + c];
    out[idx] = s;
}

// ---------------- Host orchestration ----------------
extern "C" void kernel_launch(void* const* d_in, const int* in_sizes, int n_in,
                              void* d_out, int out_size)
{
    (void)in_sizes; (void)n_in; (void)out_size;
    const float* x      = (const float*)d_in[0];
    const float* proj_w = (const float*)d_in[1];
    const float* proj_b = (const float*)d_in[2];
    const float* cls_e  = (const float*)d_in[3];
    const float* pos_e  = (const float*)d_in[4];
    const float* ln1_g  = (const float*)d_in[5];
    const float* ln1_b  = (const float*)d_in[6];
    const float* qw     = (const float*)d_in[7];
    const float* qb     = (const float*)d_in[8];
    const float* kw     = (const float*)d_in[9];
    const float* kb     = (const float*)d_in[10];
    const float* vw     = (const float*)d_in[11];
    const float* vb     = (const float*)d_in[12];
    const float* ow     = (const float*)d_in[13];
    const float* ob     = (const float*)d_in[14];
    const float* ln2_g  = (const float*)d_in[15];
    const float* ln2_b  = (const float*)d_in[16];
    const float* fcw    = (const float*)d_in[17];
    const float* fcb    = (const float*)d_in[18];
    const float* pw     = (const float*)d_in[19];
    const float* pb     = (const float*)d_in[20];
    const float* lnf_g  = (const float*)d_in[21];
    const float* lnf_b  = (const float*)d_in[22];
    const float* head_w = (const float*)d_in[23];
    const float* head_b = (const float*)d_in[24];

    __half *Wh, *Wl, *Th, *Tl, *Yh, *Yl, *Ohb, *Olb, *Mh, *Ml, *QKVh, *QKVl, *Ph, *Pl;
    float *E, *H, *Y, *S, *qkvb;
    cudaGetSymbolAddress((void**)&Wh,   g_Wh);
    cudaGetSymbolAddress((void**)&Wl,   g_Wl);
    cudaGetSymbolAddress((void**)&Th,   g_Th);
    cudaGetSymbolAddress((void**)&Tl,   g_Tl);
    cudaGetSymbolAddress((void**)&Yh,   g_Yh);
    cudaGetSymbolAddress((void**)&Yl,   g_Yl);
    cudaGetSymbolAddress((void**)&Ohb,  g_Oh);
    cudaGetSymbolAddress((void**)&Olb,  g_Ol);
    cudaGetSymbolAddress((void**)&Mh,   g_Mh);
    cudaGetSymbolAddress((void**)&Ml,   g_Ml);
    cudaGetSymbolAddress((void**)&QKVh, g_QKVh);
    cudaGetSymbolAddress((void**)&QKVl, g_QKVl);
    cudaGetSymbolAddress((void**)&Ph,   g_Ph);
    cudaGetSymbolAddress((void**)&Pl,   g_Pl);
    cudaGetSymbolAddress((void**)&E,    g_E);
    cudaGetSymbolAddress((void**)&H,    g_H);
    cudaGetSymbolAddress((void**)&Y,    g_Y);
    cudaGetSymbolAddress((void**)&S,    g_S);
    cudaGetSymbolAddress((void**)&qkvb, g_qkvb);

    static bool attr_done = false;
    if (!attr_done) {
        cudaFuncSetAttribute(attn_scores_h, cudaFuncAttributeMaxDynamicSharedMemorySize,
                             4 * 128 * SSTR * 2);
        attr_done = true;
    }
    const int SC_SMEM = 4 * 128 * SSTR * 2;   // 73728

    dim3 tb(32, 8);
    // ---- weight prep (batched over layers) ----
    const size_t WB = W_PATCH_SZ;
    transp_split_kernel<<<dim3(24, 24, 1), tb>>>(proj_w, 0, Wh, Wl, 0, 768, 768);
    transp_split_kernel<<<dim3(24, 24, LYRS), tb>>>(qw, 768 * 768, Wh + WB,               Wl + WB,               W_LAYER_SZ, 768, 768);
    transp_split_kernel<<<dim3(24, 24, LYRS), tb>>>(kw, 768 * 768, Wh + WB + 768 * 768,   Wl + WB + 768 * 768,   W_LAYER_SZ, 768, 768);
    transp_split_kernel<<<dim3(24, 24, LYRS), tb>>>(vw, 768 * 768, Wh + WB + 1536 * 768,  Wl + WB + 1536 * 768,  W_LAYER_SZ, 768, 768);
    transp_split_kernel<<<dim3(24, 24, LYRS), tb>>>(ow, 768 * 768, Wh + WB + W_O_OFF,     Wl + WB + W_O_OFF,     W_LAYER_SZ, 768, 768);
    transp_split_kernel<<<dim3(96, 24, LYRS), tb>>>(fcw, 768 * 3072, Wh + WB + W_FC_OFF,  Wl + WB + W_FC_OFF,    W_LAYER_SZ, 768, 3072);
    transp_split_kernel<<<dim3(24, 96, LYRS), tb>>>(pw, 3072 * 768,  Wh + WB + W_PW_OFF,  Wl + WB + W_PW_OFF,    W_LAYER_SZ, 3072, 768);
    biaspack_kernel<<<(LYRS * QSTR + 255) / 256, 256>>>(qb, kb, vb, qkvb);

    // ---- patch embed ----
    patch_gather_kernel<<<(PROWS * DMODEL + 255) / 256, 256>>>(x, Th, Tl);
    gemm_h_kernel<<<dim3(6, 36), 256>>>(
        Th, Tl, Wh + W_PATCH_OFF, Wl + W_PATCH_OFF, proj_b, E,
        (__half*)0, (__half*)0, PROWS, 768, 768, 0);
    assemble_kernel<<<(TOKS * DMODEL + 255) / 256, 256>>>(E, cls_e, pos_e, H);

    for (int l = 0; l < LYRS; l++) {
        size_t base = W_PATCH_SZ + (size_t)l * W_LAYER_SZ;
        const size_t bo  = (size_t)l * DMODEL;
        const size_t fbo = (size_t)l * MLPD;

        ln_split_kernel<<<TOKS, 256>>>(H, ln1_g + bo, ln1_b + bo, Yh, Yl);
        gemm_h_kernel<<<dim3(18, 37), 256>>>(
            Yh, Yl, Wh + base + W_QKV_OFF, Wl + base + W_QKV_OFF, qkvb + (size_t)l * QSTR,
            (float*)0, QKVh, QKVl, TOKS, QSTR, 768, 3);

        attn_scores_h<<<dim3(5, 5, BATCH * NHEAD), 256, SC_SMEM>>>(QKVh, QKVl, S);
        softmax_split_kernel<<<BATCH * NHEAD * NTOK, 128>>>(S, Ph, Pl);
        attn_pv_h<<<dim3(5, BATCH * NHEAD), 256>>>(Ph, Pl, QKVh, QKVl, Ohb, Olb);

        gemm_h_kernel<<<dim3(6, 37), 256>>>(
            Ohb, Olb, Wh + base + W_O_OFF, Wl + base + W_O_OFF, ob + bo,
            H, (__half*)0, (__half*)0, TOKS, 768, 768, 1);

        ln_split_kernel<<<TOKS, 256>>>(H, ln2_g + bo, ln2_b + bo, Yh, Yl);
        gemm_h_kernel<<<dim3(24, 37), 256>>>(
            Yh, Yl, Wh + base + W_FC_OFF, Wl + base + W_FC_OFF, fcb + fbo,
            (float*)0, Mh, Ml, TOKS, MLPD, 768, 2);
        gemm_h_kernel<<<dim3(6, 37), 256>>>(
            Mh, Ml, Wh + base + W_PW_OFF, Wl + base + W_PW_OFF, pb + bo,
            H, (__half*)0, (__half*)0, TOKS, 768, 3072, 1);
    }

    layernorm_kernel<<<TOKS, 256>>>(H, lnf_g, lnf_b, Y);
    head_kernel<<<(BATCH * NCLS + 255) / 256, 256>>>(Y, head_w, head_b, (float*)d_out);
}

// round 17
// speedup vs baseline: 2.5789x; 1.0254x over previous
#include <cuda_runtime.h>
#include <cuda_fp16.h>
#include <math.h>
#include <stdint.h>

// ---------------- Config ----------------
#define BATCH 8
#define CCH   3
#define IMG   384
#define NP    576
#define NTOK  577
#define DMODEL 768
#define NHEAD 12
#define HD    64
#define LYRS  12
#define MLPD  3072
#define NCLS  1000

#define TOKS   (BATCH*NTOK)      // 4616
#define TOKS_P 4736
#define PROWS  (BATCH*NP)        // 4608
#define SP     608               // padded S row stride (multiple of 32)
#define QSTR   2304              // fused QKV row stride

// Weight split buffer offsets (elements). Layout per matrix: [N][K] half.
#define W_PATCH_OFF 0
#define W_PATCH_SZ  (768*768)
#define W_LAYER_SZ  (2304*768 + 768*768 + 3072*768 + 768*3072)
#define W_QKV_OFF   0
#define W_O_OFF     (2304*768)
#define W_FC_OFF    (W_O_OFF + 768*768)
#define W_PW_OFF    (W_FC_OFF + 3072*768)
#define W_TOTAL     (W_PATCH_SZ + 12*W_LAYER_SZ)

// ---------------- Scratch ----------------
__device__ __align__(256) __half g_Wh[W_TOTAL];
__device__ __align__(256) __half g_Wl[W_TOTAL];
__device__ __align__(256) __half g_Th[PROWS*DMODEL];
__device__ __align__(256) __half g_Tl[PROWS*DMODEL];
__device__ __align__(256) __half g_Yh[TOKS_P*DMODEL];
__device__ __align__(256) __half g_Yl[TOKS_P*DMODEL];
__device__ __align__(256) __half g_Oh[TOKS_P*DMODEL];
__device__ __align__(256) __half g_Ol[TOKS_P*DMODEL];
__device__ __align__(256) __half g_Mh[(size_t)TOKS_P*MLPD];
__device__ __align__(256) __half g_Ml[(size_t)TOKS_P*MLPD];
__device__ __align__(256) __half g_QKVh[(size_t)TOKS_P*QSTR];
__device__ __align__(256) __half g_QKVl[(size_t)TOKS_P*QSTR];
__device__ __align__(256) __half g_Ph[(size_t)BATCH*NHEAD*NTOK*SP];
__device__ __align__(256) __half g_Pl[(size_t)BATCH*NHEAD*NTOK*SP];
__device__ float g_E[PROWS*DMODEL];
__device__ float g_H[TOKS*DMODEL];
__device__ float g_Y[TOKS*DMODEL];
__device__ float g_S[(size_t)BATCH*NHEAD*NTOK*SP];
__device__ float g_qkvb[LYRS*QSTR];

// ---------------- helpers ----------------
__device__ __forceinline__ uint32_t smem_u32(const void* p) {
    uint32_t a;
    asm("{ .reg .u64 t; cvta.to.shared.u64 t, %1; cvt.u32.u64 %0, t; }" : "=r"(a) : "l"(p));
    return a;
}
__device__ __forceinline__ float gelu_exact(float x) {
    return 0.5f * x * (1.0f + erff(x * 0.70710678118654752f));
}
__device__ __forceinline__ void hsplit(float x, __half& h, __half& l) {
    h = __float2half_rn(x);
    l = __float2half_rn(x - __half2float(h));
}

#define LDSM_X4(r0, r1, r2, r3, addr)                                          \
    asm volatile("ldmatrix.sync.aligned.m8n8.x4.shared.b16 {%0,%1,%2,%3}, [%4];" \
                 : "=r"(r0), "=r"(r1), "=r"(r2), "=r"(r3) : "r"(addr))
#define LDSM_X4_T(r0, r1, r2, r3, addr)                                        \
    asm volatile("ldmatrix.sync.aligned.m8n8.x4.trans.shared.b16 {%0,%1,%2,%3}, [%4];" \
                 : "=r"(r0), "=r"(r1), "=r"(r2), "=r"(r3) : "r"(addr))

#define MMA16816(d, a0, a1, a2, a3, b0, b1)                                    \
    asm volatile("mma.sync.aligned.m16n8k16.row.col.f32.f16.f16.f32 "          \
                 "{%0,%1,%2,%3},{%4,%5,%6,%7},{%8,%9},{%0,%1,%2,%3};"          \
                 : "+f"((d)[0]), "+f"((d)[1]), "+f"((d)[2]), "+f"((d)[3])      \
                 : "r"(a0), "r"(a1), "r"(a2), "r"(a3), "r"(b0), "r"(b1))

__device__ __forceinline__ void cpa16(uint32_t dst, const __half* src) {
    asm volatile("cp.async.cg.shared.global [%0], [%1], 16;" :: "r"(dst), "l"(src));
}
#define CP_COMMIT() asm volatile("cp.async.commit_group;" ::: "memory")
#define CP_WAIT0()  asm volatile("cp.async.wait_group 0;" ::: "memory")
#define CP_WAIT1()  asm volatile("cp.async.wait_group 1;" ::: "memory")

// ---------------- fp16-split HMMA GEMM (cp.async 2-stage, templated BN) ----------------
// C = A @ W^T + bias. 3 passes (hh + hl + lh), fp32 accum.
// mode 0: Cf=v+b; 1: Cf=v+b+Cf(res); 2: gelu(v+b) split->Ch/Cl; 3: (v+b) split->Ch/Cl.
// A buffers MUST be zero-padded to the grid's M coverage (they are: static globals).
#define ASTR 40

template<int BN>
__global__ __launch_bounds__(256, 1) void gemm_h_kernel(
    const __half* __restrict__ Ah, const __half* __restrict__ Al,
    const __half* __restrict__ Wh, const __half* __restrict__ Wl,
    const float* __restrict__ bias, float* Cf,
    __half* __restrict__ Ch, __half* __restrict__ Cl,
    int M, int N, int K, int mode)
{
    extern __shared__ __half smh[];
    constexpr int NBF = BN / 32;           // B ldmatrix groups per warp (4 or 2)
    constexpr int JJN = BN / 16;           // mma jj count per warp (8 or 4)
    constexpr int STG = (256 + 2 * BN) * ASTR;   // stage size in halves
    constexpr int OF_AL = 128 * ASTR;
    constexpr int OF_BH = 256 * ASTR;
    constexpr int OF_BL = (256 + BN) * ASTR;

    const int tid  = threadIdx.x;
    const int lane = tid & 31;
    const int w    = tid >> 5;
    const int wm   = w & 3;
    const int wn   = w >> 2;
    const int bm = blockIdx.y * 128;
    const int bn = blockIdx.x * BN;

    const uint32_t smBase = smem_u32(smh);

    // loader mapping: float4 over rows x (32 halves): idx -> row=idx>>2, c8=(idx&3)*8
    const int lr0 = tid >> 2,         lc0 = (tid & 3) * 8;
    const int lr1 = (tid + 256) >> 2; // for 128-row tiles

    const int arow = wm * 32 + (lane & 15);
    const int acol = (lane >> 4) * 8;
    const int brow_base = wn * (BN / 2) + (lane & 7) + ((lane >> 4) << 3);
    const int bcol = (lane & 8);

    float acc[2][JJN][4];
#pragma unroll
    for (int i = 0; i < 2; i++)
#pragma unroll
        for (int j = 0; j < JJN; j++)
#pragma unroll
            for (int q = 0; q < 4; q++) acc[i][j][q] = 0.f;

    const int nt = K >> 5;

    // stage loader
    auto load_stage = [&](int t, int buf) {
        const int k0 = t << 5;
        const uint32_t sb = smBase + buf * (STG * 2);
        // A hi/lo: 128 rows
        cpa16(sb + (lr0 * ASTR + lc0) * 2,            Ah + (size_t)(bm + lr0) * K + k0 + lc0);
        cpa16(sb + (lr1 * ASTR + lc0) * 2,            Ah + (size_t)(bm + lr1) * K + k0 + lc0);
        cpa16(sb + (OF_AL + lr0 * ASTR + lc0) * 2,    Al + (size_t)(bm + lr0) * K + k0 + lc0);
        cpa16(sb + (OF_AL + lr1 * ASTR + lc0) * 2,    Al + (size_t)(bm + lr1) * K + k0 + lc0);
        // B hi/lo: BN rows
        cpa16(sb + (OF_BH + lr0 * ASTR + lc0) * 2,    Wh + (size_t)(bn + lr0) * K + k0 + lc0);
        cpa16(sb + (OF_BL + lr0 * ASTR + lc0) * 2,    Wl + (size_t)(bn + lr0) * K + k0 + lc0);
        if (BN == 128) {
            cpa16(sb + (OF_BH + lr1 * ASTR + lc0) * 2, Wh + (size_t)(bn + lr1) * K + k0 + lc0);
            cpa16(sb + (OF_BL + lr1 * ASTR + lc0) * 2, Wl + (size_t)(bn + lr1) * K + k0 + lc0);
        }
    };

    load_stage(0, 0);
    CP_COMMIT();

    for (int t = 0; t < nt; t++) {
        const int buf = t & 1;
        const bool more = (t + 1 < nt);
        if (more) {
            load_stage(t + 1, buf ^ 1);
            CP_COMMIT();
            CP_WAIT1();
        } else {
            CP_WAIT0();
        }
        __syncthreads();

        const uint32_t sb = smBase + buf * (STG * 2);
        const uint32_t uAh = sb, uAl = sb + OF_AL * 2;
        const uint32_t uBh = sb + OF_BH * 2, uBl = sb + OF_BL * 2;

#pragma unroll
        for (int k16 = 0; k16 < 2; k16++) {
            const int kc = k16 * 16;
            uint32_t ah[2][4], al2[2][4];
#pragma unroll
            for (int am = 0; am < 2; am++) {
                uint32_t off = ((arow + am * 16) * ASTR + kc + acol) * 2;
                LDSM_X4(ah[am][0], ah[am][1], ah[am][2], ah[am][3], uAh + off);
                LDSM_X4(al2[am][0], al2[am][1], al2[am][2], al2[am][3], uAl + off);
            }
            uint32_t bh[NBF][4], bl[NBF][4];
#pragma unroll
            for (int j = 0; j < NBF; j++) {
                uint32_t off = ((brow_base + j * 16) * ASTR + kc + bcol) * 2;
                LDSM_X4(bh[j][0], bh[j][1], bh[j][2], bh[j][3], uBh + off);
                LDSM_X4(bl[j][0], bl[j][1], bl[j][2], bl[j][3], uBl + off);
            }
#pragma unroll
            for (int am = 0; am < 2; am++) {
#pragma unroll
                for (int jj = 0; jj < JJN; jj++) {
                    const int jx = jj >> 1, sel = (jj & 1) * 2;
                    MMA16816(acc[am][jj], ah[am][0], ah[am][1], ah[am][2], ah[am][3],
                             bh[jx][sel], bh[jx][sel + 1]);
                    MMA16816(acc[am][jj], ah[am][0], ah[am][1], ah[am][2], ah[am][3],
                             bl[jx][sel], bl[jx][sel + 1]);
                    MMA16816(acc[am][jj], al2[am][0], al2[am][1], al2[am][2], al2[am][3],
                             bh[jx][sel], bh[jx][sel + 1]);
                }
            }
        }
        if (more) __syncthreads();
    }

    // ---- epilogue ----
    const int gRow0 = bm + wm * 32 + (lane >> 2);
    const int gCol0 = bn + wn * (BN / 2) + (lane & 3) * 2;
#pragma unroll
    for (int am = 0; am < 2; am++) {
#pragma unroll
        for (int jj = 0; jj < JJN; jj++) {
            const int gc = gCol0 + jj * 8;
            const float2 b2 = *(const float2*)(bias + gc);
#pragma unroll
            for (int hrow = 0; hrow < 2; hrow++) {
                const int gr = gRow0 + am * 16 + hrow * 8;
                if (gr >= M) continue;
                float x0 = acc[am][jj][hrow * 2 + 0] + b2.x;
                float x1 = acc[am][jj][hrow * 2 + 1] + b2.y;
                if (mode <= 1) {
                    if (mode == 1) {
                        float2 rv = *(const float2*)(Cf + (size_t)gr * N + gc);
                        x0 += rv.x; x1 += rv.y;
                    }
                    *(float2*)(Cf + (size_t)gr * N + gc) = make_float2(x0, x1);
                } else {
                    if (mode == 2) { x0 = gelu_exact(x0); x1 = gelu_exact(x1); }
                    __half h0, l0, h1, l1;
                    hsplit(x0, h0, l0); hsplit(x1, h1, l1);
                    *(__half2*)(Ch + (size_t)gr * N + gc) = __halves2half2(h0, h1);
                    *(__half2*)(Cl + (size_t)gr * N + gc) = __halves2half2(l0, l1);
                }
            }
        }
    }
}

// ---------------- Attention scores: S = scale * Q @ K^T (HMMA, 3-pass split) ----------------
#define SSTR 72
__global__ __launch_bounds__(256, 1) void attn_scores_h(
    const __half* __restrict__ QKVh, const __half* __restrict__ QKVl,
    float* __restrict__ S)
{
    extern __shared__ __half sm[];
    __half* sQh = sm;
    __half* sQl = sm + 128 * SSTR;
    __half* sKh = sm + 2 * 128 * SSTR;
    __half* sKl = sm + 3 * 128 * SSTR;

    const int bh = blockIdx.z;
    const int b = bh / NHEAD, h = bh - b * NHEAD;
    const int m0 = blockIdx.y * 128, n0 = blockIdx.x * 128;
    const int tid = threadIdx.x, lane = tid & 31, w = tid >> 5;
    const int wm = w & 3, wn = w >> 2;

    const size_t qoff = (size_t)b * NTOK * QSTR + h * HD;
    const size_t koff = qoff + 768;

#pragma unroll
    for (int i = 0; i < 4; i++) {
        int idx = tid + i * 256;
        int r = idx >> 3, c8 = (idx & 7) * 8;
        float4 z4 = make_float4(0.f, 0.f, 0.f, 0.f);
        float4 qh = z4, ql = z4, kh = z4, kl = z4;
        if (m0 + r < NTOK) {
            qh = *(const float4*)(QKVh + qoff + (size_t)(m0 + r) * QSTR + c8);
            ql = *(const float4*)(QKVl + qoff + (size_t)(m0 + r) * QSTR + c8);
        }
        if (n0 + r < NTOK) {
            kh = *(const float4*)(QKVh + koff + (size_t)(n0 + r) * QSTR + c8);
            kl = *(const float4*)(QKVl + koff + (size_t)(n0 + r) * QSTR + c8);
        }
        *(float4*)&sQh[r * SSTR + c8] = qh;
        *(float4*)&sQl[r * SSTR + c8] = ql;
        *(float4*)&sKh[r * SSTR + c8] = kh;
        *(float4*)&sKl[r * SSTR + c8] = kl;
    }
    __syncthreads();

    const uint32_t uQh = smem_u32(sQh), uQl = smem_u32(sQl);
    const uint32_t uKh = smem_u32(sKh), uKl = smem_u32(sKl);
    const int arow = wm * 32 + (lane & 15);
    const int acol = (lane >> 4) * 8;
    const int brow_base = wn * 64 + (lane & 7) + ((lane >> 4) << 3);
    const int bcol = (lane & 8);

    float acc[2][8][4];
#pragma unroll
    for (int i = 0; i < 2; i++)
#pragma unroll
        for (int j = 0; j < 8; j++)
#pragma unroll
            for (int q = 0; q < 4; q++) acc[i][j][q] = 0.f;

#pragma unroll
    for (int k16 = 0; k16 < 4; k16++) {
        const int kc = k16 * 16;
        uint32_t ah[2][4], al2[2][4];
#pragma unroll
        for (int am = 0; am < 2; am++) {
            uint32_t off = ((arow + am * 16) * SSTR + kc + acol) * 2;
            LDSM_X4(ah[am][0], ah[am][1], ah[am][2], ah[am][3], uQh + off);
            LDSM_X4(al2[am][0], al2[am][1], al2[am][2], al2[am][3], uQl + off);
        }
        uint32_t bhf[4][4], blf[4][4];
#pragma unroll
        for (int j = 0; j < 4; j++) {
            uint32_t off = ((brow_base + j * 16) * SSTR + kc + bcol) * 2;
            LDSM_X4(bhf[j][0], bhf[j][1], bhf[j][2], bhf[j][3], uKh + off);
            LDSM_X4(blf[j][0], blf[j][1], blf[j][2], blf[j][3], uKl + off);
        }
#pragma unroll
        for (int am = 0; am < 2; am++) {
#pragma unroll
            for (int jj = 0; jj < 8; jj++) {
                const int jx = jj >> 1, sel = (jj & 1) * 2;
                MMA16816(acc[am][jj], ah[am][0], ah[am][1], ah[am][2], ah[am][3],
                         bhf[jx][sel], bhf[jx][sel + 1]);
                MMA16816(acc[am][jj], ah[am][0], ah[am][1], ah[am][2], ah[am][3],
                         blf[jx][sel], blf[jx][sel + 1]);
                MMA16816(acc[am][jj], al2[am][0], al2[am][1], al2[am][2], al2[am][3],
                         bhf[jx][sel], bhf[jx][sel + 1]);
            }
        }
    }

    float* Sb = S + (size_t)bh * NTOK * SP;
    const int gr0 = m0 + wm * 32 + (lane >> 2);
    const int gc0 = n0 + wn * 64 + (lane & 3) * 2;
#pragma unroll
    for (int am = 0; am < 2; am++) {
#pragma unroll
        for (int hrow = 0; hrow < 2; hrow++) {
            const int gr = gr0 + am * 16 + hrow * 8;
            if (gr >= NTOK) continue;
#pragma unroll
            for (int jj = 0; jj < 8; jj++) {
                const int gc = gc0 + jj * 8;
                if (gc >= NTOK) continue;
                *(float2*)(Sb + (size_t)gr * SP + gc) =
                    make_float2(acc[am][jj][hrow * 2] * 0.125f,
                                acc[am][jj][hrow * 2 + 1] * 0.125f);
            }
        }
    }
}

// ---------------- Softmax: fp32 S row -> split halves Ph/Pl (pads zeroed) ----------------
__global__ void softmax_split_kernel(const float* __restrict__ S,
                                     __half* __restrict__ Ph, __half* __restrict__ Pl)
{
    int r  = blockIdx.x;
    int bh = r / NTOK, m = r - bh * NTOK;
    const size_t ro = (size_t)bh * NTOK * SP + (size_t)m * SP;
    const float* row = S + ro;
    int tid = threadIdx.x;   // 128

    float lmax = -3.4e38f;
    for (int c = tid; c < NTOK; c += 128) lmax = fmaxf(lmax, row[c]);
#pragma unroll
    for (int o = 16; o; o >>= 1) lmax = fmaxf(lmax, __shfl_xor_sync(0xffffffffu, lmax, o));
    __shared__ float sred[4];
    if ((tid & 31) == 0) sred[tid >> 5] = lmax;
    __syncthreads();
    float bmax = fmaxf(fmaxf(sred[0], sred[1]), fmaxf(sred[2], sred[3]));
    __syncthreads();

    float ev[5];
    float lsum = 0.f;
    int cnt = 0;
    for (int c = tid; c < NTOK; c += 128) {
        float e = expf(row[c] - bmax);
        ev[cnt++] = e;
        lsum += e;
    }
#pragma unroll
    for (int o = 16; o; o >>= 1) lsum += __shfl_xor_sync(0xffffffffu, lsum, o);
    if ((tid & 31) == 0) sred[tid >> 5] = lsum;
    __syncthreads();
    float inv = 1.0f / (sred[0] + sred[1] + sred[2] + sred[3]);

    cnt = 0;
    for (int c = tid; c < NTOK; c += 128) {
        __half hh, ll;
        hsplit(ev[cnt++] * inv, hh, ll);
        Ph[ro + c] = hh;
        Pl[ro + c] = ll;
    }
    if (tid < SP - NTOK) {
        Ph[ro + NTOK + tid] = __float2half(0.f);
        Pl[ro + NTOK + tid] = __float2half(0.f);
    }
}

// ---------------- PV: O = P @ V (HMMA, 3-pass split, V via ldmatrix.trans) ----------------
#define VSTR 72
__global__ __launch_bounds__(256, 1) void attn_pv_h(
    const __half* __restrict__ Ph, const __half* __restrict__ Pl,
    const __half* __restrict__ QKVh, const __half* __restrict__ QKVl,
    __half* __restrict__ Oh, __half* __restrict__ Ol)
{
    __shared__ __half sPh[128 * ASTR];
    __shared__ __half sPl[128 * ASTR];
    __shared__ __half sVh[32 * VSTR];
    __shared__ __half sVl[32 * VSTR];

    const int bh = blockIdx.y;
    const int b = bh / NHEAD, h = bh - b * NHEAD;
    const int m0 = blockIdx.x * 128;
    const int tid = threadIdx.x, lane = tid & 31, w = tid >> 5;
    const int wm = w & 3, wn = w >> 2;

    const size_t pbase = (size_t)bh * NTOK * SP;
    const size_t vbase = (size_t)b * NTOK * QSTR + 1536 + h * HD;

    const uint32_t uPh = smem_u32(sPh), uPl = smem_u32(sPl);
    const uint32_t uVh = smem_u32(sVh), uVl = smem_u32(sVl);

    float acc[2][4][4];
#pragma unroll
    for (int i = 0; i < 2; i++)
#pragma unroll
        for (int j = 0; j < 4; j++)
#pragma unroll
            for (int q = 0; q < 4; q++) acc[i][j][q] = 0.f;

    const int arow = wm * 32 + (lane & 15);
    const int acol = (lane >> 4) * 8;
    const int bk   = (lane & 7) + ((lane >> 3) & 1) * 8;
    const int bn_  = wn * 32 + (lane >> 4) * 8;

    for (int k0 = 0; k0 < SP; k0 += 32) {
#pragma unroll
        for (int i = 0; i < 2; i++) {
            int idx = tid + i * 256;
            int r = idx >> 2, c8 = (idx & 3) * 8;
            float4 p4 = make_float4(0.f, 0.f, 0.f, 0.f), q4 = p4;
            if (m0 + r < NTOK) {
                p4 = *(const float4*)(Ph + pbase + (size_t)(m0 + r) * SP + k0 + c8);
                q4 = *(const float4*)(Pl + pbase + (size_t)(m0 + r) * SP + k0 + c8);
            }
            *(float4*)&sPh[r * ASTR + c8] = p4;
            *(float4*)&sPl[r * ASTR + c8] = q4;
        }
        {
            int r = tid >> 3, c8 = (tid & 7) * 8;
            float4 v4 = make_float4(0.f, 0.f, 0.f, 0.f), u4 = v4;
            if (k0 + r < NTOK) {
                v4 = *(const float4*)(QKVh + vbase + (size_t)(k0 + r) * QSTR + c8);
                u4 = *(const float4*)(QKVl + vbase + (size_t)(k0 + r) * QSTR + c8);
            }
            *(float4*)&sVh[r * VSTR + c8] = v4;
            *(float4*)&sVl[r * VSTR + c8] = u4;
        }
        __syncthreads();

#pragma unroll
        for (int k16 = 0; k16 < 2; k16++) {
            const int kc = k16 * 16;
            uint32_t ah[2][4], al2[2][4];
#pragma unroll
            for (int am = 0; am < 2; am++) {
                uint32_t off = ((arow + am * 16) * ASTR + kc + acol) * 2;
                LDSM_X4(ah[am][0], ah[am][1], ah[am][2], ah[am][3], uPh + off);
                LDSM_X4(al2[am][0], al2[am][1], al2[am][2], al2[am][3], uPl + off);
            }
            uint32_t bhf[2][4], blf[2][4];
#pragma unroll
            for (int j = 0; j < 2; j++) {
                uint32_t off = ((kc + bk) * VSTR + bn_ + j * 16) * 2;
                LDSM_X4_T(bhf[j][0], bhf[j][1], bhf[j][2], bhf[j][3], uVh + off);
                LDSM_X4_T(blf[j][0], blf[j][1], blf[j][2], blf[j][3], uVl + off);
            }
#pragma unroll
            for (int am = 0; am < 2; am++) {
#pragma unroll
                for (int jj = 0; jj < 4; jj++) {
                    const int jx = jj >> 1, sel = (jj & 1) * 2;
                    MMA16816(acc[am][jj], ah[am][0], ah[am][1], ah[am][2], ah[am][3],
                             bhf[jx][sel], bhf[jx][sel + 1]);
                    MMA16816(acc[am][jj], ah[am][0], ah[am][1], ah[am][2], ah[am][3],
                             blf[jx][sel], blf[jx][sel + 1]);
                    MMA16816(acc[am][jj], al2[am][0], al2[am][1], al2[am][2], al2[am][3],
                             bhf[jx][sel], bhf[jx][sel + 1]);
                }
            }
        }
        __syncthreads();
    }

    const int gr0 = m0 + wm * 32 + (lane >> 2);
    const int gc0 = wn * 32 + (lane & 3) * 2;
#pragma unroll
    for (int am = 0; am < 2; am++) {
#pragma unroll
        for (int hrow = 0; hrow < 2; hrow++) {
            const int gr = gr0 + am * 16 + hrow * 8;
            if (gr >= NTOK) continue;
            const size_t rbase = ((size_t)(b * NTOK + gr)) * DMODEL + h * HD;
#pragma unroll
            for (int jj = 0; jj < 4; jj++) {
                const int gc = gc0 + jj * 8;
                __half h0, l0, h1, l1;
                hsplit(acc[am][jj][hrow * 2 + 0], h0, l0);
                hsplit(acc[am][jj][hrow * 2 + 1], h1, l1);
                *(__half2*)(Oh + rbase + gc) = __halves2half2(h0, h1);
                *(__half2*)(Ol + rbase + gc) = __halves2half2(l0, l1);
            }
        }
    }
}

// ---------------- Weight transpose + split (batched over layers via grid.z) ----------------
__global__ void transp_split_kernel(const float* __restrict__ src, size_t srcStride,
                                    __half* __restrict__ dh, __half* __restrict__ dl,
                                    size_t dstStride, int K, int N)
{
    __shared__ float t[32][33];
    const float* s = src + (size_t)blockIdx.z * srcStride;
    __half* dhh = dh + (size_t)blockIdx.z * dstStride;
    __half* dll = dl + (size_t)blockIdx.z * dstStride;
    int k0 = blockIdx.y * 32, n0 = blockIdx.x * 32;
    int tx = threadIdx.x, ty = threadIdx.y;
#pragma unroll
    for (int j = 0; j < 4; j++)
        t[ty + j * 8][tx] = s[(size_t)(k0 + ty + j * 8) * N + n0 + tx];
    __syncthreads();
#pragma unroll
    for (int j = 0; j < 4; j++) {
        int n = n0 + ty + j * 8;
        float v = t[tx][ty + j * 8];
        __half h, l; hsplit(v, h, l);
        dhh[(size_t)n * K + k0 + tx] = h;
        dll[(size_t)n * K + k0 + tx] = l;
    }
}

// ---------------- QKV bias pack ----------------
__global__ void biaspack_kernel(const float* qb, const float* kb, const float* vb, float* out)
{
    int idx = blockIdx.x * blockDim.x + threadIdx.x;
    if (idx >= LYRS * QSTR) return;
    int l = idx / QSTR, c = idx - l * QSTR;
    float v = (c < 768) ? qb[l * 768 + c] : (c < 1536) ? kb[l * 768 + c - 768] : vb[l * 768 + c - 1536];
    out[idx] = v;
}

// ---------------- Patch gather (faithful buggy flattening) + split ----------------
__global__ void patch_gather_kernel(const float* __restrict__ x,
                                    __half* __restrict__ Th, __half* __restrict__ Tl)
{
    int idx = blockIdx.x * blockDim.x + threadIdx.x;
    if (idx >= PROWS * DMODEL) return;
    int p1  = idx / 221184;
    int rem = idx % 221184;
    int m   = rem >> 4;
    int p2  = rem & 15;
    int b   = m / 1728;
    int mm  = m - b * 1728;
    int c   = mm / 576;
    int mg  = mm - c * 576;
    int gh  = mg / 24;
    int gw  = mg - gh * 24;
    float v = x[(((size_t)(b * CCH + c) * IMG) + gh * 16 + p1) * IMG + gw * 16 + p2];
    __half h, l; hsplit(v, h, l);
    Th[idx] = h; Tl[idx] = l;
}

// ---------------- Assemble tokens ----------------
__global__ void assemble_kernel(const float* __restrict__ E, const float* __restrict__ cls,
                                const float* __restrict__ pos, float* __restrict__ H)
{
    int idx = blockIdx.x * blockDim.x + threadIdx.x;
    if (idx >= TOKS * DMODEL) return;
    int tok = idx / DMODEL;
    int k   = idx - tok * DMODEL;
    int b   = tok / NTOK;
    int n   = tok - b * NTOK;
    float v = (n == 0) ? cls[k] : E[((size_t)(b * NP + n - 1)) * DMODEL + k];
    H[idx] = v + pos[(size_t)n * DMODEL + k];
}

// ---------------- LayerNorm: split output ----------------
__global__ void ln_split_kernel(const float* __restrict__ X, const float* __restrict__ g,
                                const float* __restrict__ bta,
                                __half* __restrict__ Yh, __half* __restrict__ Yl)
{
    int r = blockIdx.x;
    const float* xr = X + (size_t)r * DMODEL;
    int tid = threadIdx.x;
    float v0 = xr[tid], v1 = xr[tid + 256], v2 = xr[tid + 512];
    float s  = v0 + v1 + v2;
    float s2 = v0 * v0 + v1 * v1 + v2 * v2;
#pragma unroll
    for (int o = 16; o; o >>= 1) {
        s  += __shfl_xor_sync(0xffffffffu, s,  o);
        s2 += __shfl_xor_sync(0xffffffffu, s2, o);
    }
    __shared__ float r1[8], r2[8];
    if ((tid & 31) == 0) { r1[tid >> 5] = s; r2[tid >> 5] = s2; }
    __syncthreads();
    float S = 0.f, S2 = 0.f;
#pragma unroll
    for (int ww = 0; ww < 8; ww++) { S += r1[ww]; S2 += r2[ww]; }
    float mean = S * (1.0f / 768.0f);
    float var  = S2 * (1.0f / 768.0f) - mean * mean;
    float inv  = rsqrtf(var + 1e-5f);
#pragma unroll
    for (int j = 0; j < 3; j++) {
        int c = tid + j * 256;
        float y = (xr[c] - mean) * inv * g[c] + bta[c];
        __half h, l; hsplit(y, h, l);
        Yh[(size_t)r * DMODEL + c] = h;
        Yl[(size_t)r * DMODEL + c] = l;
    }
}

// ---------------- LayerNorm fp32 out (final) ----------------
__global__ void layernorm_kernel(const float* __restrict__ X, const float* __restrict__ g,
                                 const float* __restrict__ bta, float* __restrict__ Y)
{
    int r = blockIdx.x;
    const float* xr = X + (size_t)r * DMODEL;
    float* yr = Y + (size_t)r * DMODEL;
    int tid = threadIdx.x;
    float v0 = xr[tid], v1 = xr[tid + 256], v2 = xr[tid + 512];
    float s  = v0 + v1 + v2;
    float s2 = v0 * v0 + v1 * v1 + v2 * v2;
#pragma unroll
    for (int o = 16; o; o >>= 1) {
        s  += __shfl_xor_sync(0xffffffffu, s,  o);
        s2 += __shfl_xor_sync(0xffffffffu, s2, o);
    }
    __shared__ float r1[8], r2[8];
    if ((tid & 31) == 0) { r1[tid >> 5] = s; r2[tid >> 5] = s2; }
    __syncthreads();
    float S = 0.f, S2 = 0.f;
#pragma unroll
    for (int ww = 0; ww < 8; ww++) { S += r1[ww]; S2 += r2[ww]; }
    float mean = S * (1.0f / 768.0f);
    float var  = S2 * (1.0f / 768.0f) - mean * mean;
    float inv  = rsqrtf(var + 1e-5f);
    yr[tid]       = (v0 - mean) * inv * g[tid]       + bta[tid];
    yr[tid + 256] = (v1 - mean) * inv * g[tid + 256] + bta[tid + 256];
    yr[tid + 512] = (v2 - mean) * inv * g[tid + 512] + bta[tid + 512];
}

// ---------------- Classifier head ----------------
__global__ void head_kernel(const float* __restrict__ Hln, const float* __restrict__ W,
                            const float* __restrict__ bias, float* __restrict__ out)
{
    int idx = blockIdx.x * blockDim.x + threadIdx.x;
    if (idx >= BATCH * NCLS) return;
    int b = idx / NCLS, c = idx - b * NCLS;
    const float* hr = Hln + (size_t)b * NTOK * DMODEL;
    float s = bias[c];
#pragma unroll 4
    for (int d = 0; d < DMODEL; d++) s += hr[d] * W[(size_t)d * NCLS + c];
    out[idx] = s;
}

// ---------------- Host orchestration ----------------
extern "C" void kernel_launch(void* const* d_in, const int* in_sizes, int n_in,
                              void* d_out, int out_size)
{
    (void)in_sizes; (void)n_in; (void)out_size;
    const float* x      = (const float*)d_in[0];
    const float* proj_w = (const float*)d_in[1];
    const float* proj_b = (const float*)d_in[2];
    const float* cls_e  = (const float*)d_in[3];
    const float* pos_e  = (const float*)d_in[4];
    const float* ln1_g  = (const float*)d_in[5];
    const float* ln1_b  = (const float*)d_in[6];
    const float* qw     = (const float*)d_in[7];
    const float* qb     = (const float*)d_in[8];
    const float* kw     = (const float*)d_in[9];
    const float* kb     = (const float*)d_in[10];
    const float* vw     = (const float*)d_in[11];
    const float* vb     = (const float*)d_in[12];
    const float* ow     = (const float*)d_in[13];
    const float* ob     = (const float*)d_in[14];
    const float* ln2_g  = (const float*)d_in[15];
    const float* ln2_b  = (const float*)d_in[16];
    const float* fcw    = (const float*)d_in[17];
    const float* fcb    = (const float*)d_in[18];
    const float* pw     = (const float*)d_in[19];
    const float* pb     = (const float*)d_in[20];
    const float* lnf_g  = (const float*)d_in[21];
    const float* lnf_b  = (const float*)d_in[22];
    const float* head_w = (const float*)d_in[23];
    const float* head_b = (const float*)d_in[24];

    __half *Wh, *Wl, *Th, *Tl, *Yh, *Yl, *Ohb, *Olb, *Mh, *Ml, *QKVh, *QKVl, *Ph, *Pl;
    float *E, *H, *Y, *S, *qkvb;
    cudaGetSymbolAddress((void**)&Wh,   g_Wh);
    cudaGetSymbolAddress((void**)&Wl,   g_Wl);
    cudaGetSymbolAddress((void**)&Th,   g_Th);
    cudaGetSymbolAddress((void**)&Tl,   g_Tl);
    cudaGetSymbolAddress((void**)&Yh,   g_Yh);
    cudaGetSymbolAddress((void**)&Yl,   g_Yl);
    cudaGetSymbolAddress((void**)&Ohb,  g_Oh);
    cudaGetSymbolAddress((void**)&Olb,  g_Ol);
    cudaGetSymbolAddress((void**)&Mh,   g_Mh);
    cudaGetSymbolAddress((void**)&Ml,   g_Ml);
    cudaGetSymbolAddress((void**)&QKVh, g_QKVh);
    cudaGetSymbolAddress((void**)&QKVl, g_QKVl);
    cudaGetSymbolAddress((void**)&Ph,   g_Ph);
    cudaGetSymbolAddress((void**)&Pl,   g_Pl);
    cudaGetSymbolAddress((void**)&E,    g_E);
    cudaGetSymbolAddress((void**)&H,    g_H);
    cudaGetSymbolAddress((void**)&Y,    g_Y);
    cudaGetSymbolAddress((void**)&S,    g_S);
    cudaGetSymbolAddress((void**)&qkvb, g_qkvb);

    const int SM128 = (256 + 256) * ASTR * 2 * 2;   // 81920 B
    const int SM64  = (256 + 128) * ASTR * 2 * 2;   // 61440 B
    const int SC_SMEM = 4 * 128 * SSTR * 2;         // 73728 B
    static bool attr_done = false;
    if (!attr_done) {
        cudaFuncSetAttribute(gemm_h_kernel<128>, cudaFuncAttributeMaxDynamicSharedMemorySize, SM128);
        cudaFuncSetAttribute(gemm_h_kernel<64>,  cudaFuncAttributeMaxDynamicSharedMemorySize, SM64);
        cudaFuncSetAttribute(attn_scores_h, cudaFuncAttributeMaxDynamicSharedMemorySize, SC_SMEM);
        attr_done = true;
    }

    dim3 tb(32, 8);
    // ---- weight prep (batched over layers) ----
    const size_t WB = W_PATCH_SZ;
    transp_split_kernel<<<dim3(24, 24, 1), tb>>>(proj_w, 0, Wh, Wl, 0, 768, 768);
    transp_split_kernel<<<dim3(24, 24, LYRS), tb>>>(qw, 768 * 768, Wh + WB,               Wl + WB,               W_LAYER_SZ, 768, 768);
    transp_split_kernel<<<dim3(24, 24, LYRS), tb>>>(kw, 768 * 768, Wh + WB + 768 * 768,   Wl + WB + 768 * 768,   W_LAYER_SZ, 768, 768);
    transp_split_kernel<<<dim3(24, 24, LYRS), tb>>>(vw, 768 * 768, Wh + WB + 1536 * 768,  Wl + WB + 1536 * 768,  W_LAYER_SZ, 768, 768);
    transp_split_kernel<<<dim3(24, 24, LYRS), tb>>>(ow, 768 * 768, Wh + WB + W_O_OFF,     Wl + WB + W_O_OFF,     W_LAYER_SZ, 768, 768);
    transp_split_kernel<<<dim3(96, 24, LYRS), tb>>>(fcw, 768 * 3072, Wh + WB + W_FC_OFF,  Wl + WB + W_FC_OFF,    W_LAYER_SZ, 768, 3072);
    transp_split_kernel<<<dim3(24, 96, LYRS), tb>>>(pw, 3072 * 768,  Wh + WB + W_PW_OFF,  Wl + WB + W_PW_OFF,    W_LAYER_SZ, 3072, 768);
    biaspack_kernel<<<(LYRS * QSTR + 255) / 256, 256>>>(qb, kb, vb, qkvb);

    // ---- patch embed (N=768, BN=64 -> 12x36=432 CTAs, ~3 waves) ----
    patch_gather_kernel<<<(PROWS * DMODEL + 255) / 256, 256>>>(x, Th, Tl);
    gemm_h_kernel<64><<<dim3(12, 36), 256, SM64>>>(
        Th, Tl, Wh + W_PATCH_OFF, Wl + W_PATCH_OFF, proj_b, E,
        (__half*)0, (__half*)0, PROWS, 768, 768, 0);
    assemble_kernel<<<(TOKS * DMODEL + 255) / 256, 256>>>(E, cls_e, pos_e, H);

    for (int l = 0; l < LYRS; l++) {
        size_t base = W_PATCH_SZ + (size_t)l * W_LAYER_SZ;
        const size_t bo  = (size_t)l * DMODEL;
        const size_t fbo = (size_t)l * MLPD;

        ln_split_kernel<<<TOKS, 256>>>(H, ln1_g + bo, ln1_b + bo, Yh, Yl);
        gemm_h_kernel<128><<<dim3(18, 37), 256, SM128>>>(
            Yh, Yl, Wh + base + W_QKV_OFF, Wl + base + W_QKV_OFF, qkvb + (size_t)l * QSTR,
            (float*)0, QKVh, QKVl, TOKS, QSTR, 768, 3);

        attn_scores_h<<<dim3(5, 5, BATCH * NHEAD), 256, SC_SMEM>>>(QKVh, QKVl, S);
        softmax_split_kernel<<<BATCH * NHEAD * NTOK, 128>>>(S, Ph, Pl);
        attn_pv_h<<<dim3(5, BATCH * NHEAD), 256>>>(Ph, Pl, QKVh, QKVl, Ohb, Olb);

        // O-proj: N=768, BN=64 -> 12x37=444 CTAs = 3.0 waves
        gemm_h_kernel<64><<<dim3(12, 37), 256, SM64>>>(
            Ohb, Olb, Wh + base + W_O_OFF, Wl + base + W_O_OFF, ob + bo,
            H, (__half*)0, (__half*)0, TOKS, 768, 768, 1);

        ln_split_kernel<<<TOKS, 256>>>(H, ln2_g + bo, ln2_b + bo, Yh, Yl);
        gemm_h_kernel<128><<<dim3(24, 37), 256, SM128>>>(
            Yh, Yl, Wh + base + W_FC_OFF, Wl + base + W_FC_OFF, fcb + fbo,
            (float*)0, Mh, Ml, TOKS, MLPD, 768, 2);
        // pw: N=768, K=3072, BN=64 -> 444 CTAs = 3.0 waves
        gemm_h_kernel<64><<<dim3(12, 37), 256, SM64>>>(
            Mh, Ml, Wh + base + W_PW_OFF, Wl + base + W_PW_OFF, pb + bo,
            H, (__half*)0, (__half*)0, TOKS, 768, 3072, 1);
    }

    layernorm_kernel<<<TOKS, 256>>>(H, lnf_g, lnf_b, Y);
    head_kernel<<<(BATCH * NCLS + 255) / 256, 256>>>(Y, head_w, head_b, (float*)d_out);
}